// round 6
// baseline (speedup 1.0000x reference)
#include <cuda_runtime.h>
#include <math.h>

// Problem constants
#define NSIG 256          // B*C = 128*2 signals
#define LSIG 65537        // signal length (== RLEN)
#define N2   65536        // packed complex FFT length (NFFT/2)
#define RS   257          // smem row stride in float2 (kf1/ki2)
#define RSZ  257          // smem row stride in float2 (kmid)
#define MSS  257          // magnitude row stride (floats)
#define NC   16           // central rows per kmid block
#define NSL  18           // NC+2 forward slots

// Scratch (allowed: __device__ globals, no allocation)
__device__ float2 g_buf1[(size_t)NSIG * N2];   // 134 MB
__device__ float2 g_buf2[(size_t)NSIG * N2];   // 134 MB
__device__ float  g_gainT[65536];              // gain transposed: [r*256+c] = gain[r+256c]
__device__ float  g_g65536;                    // gain at bin 65536
__device__ float  g_pm;

__device__ __forceinline__ float2 cmulf(float2 a, float2 b) {
    return make_float2(a.x*b.x - a.y*b.y, a.x*b.y + a.y*b.x);
}

// ---------------------------------------------------------------------------
// Register-resident 16-point FFT (Stockham radix-2, natural order in/out).
// ---------------------------------------------------------------------------
template<int SGN, int M>
__device__ __forceinline__ void fstage16(const float2* A, float2* B) {
    const float CU[8] = {1.f, 0.92387953251f, 0.70710678119f, 0.38268343236f,
                         0.f, -0.38268343236f, -0.70710678119f, -0.92387953251f};
    const float SU[8] = {0.f, 0.38268343236f, 0.70710678119f, 0.92387953251f,
                         1.f, 0.92387953251f, 0.70710678119f, 0.38268343236f};
#pragma unroll
    for (int t = 0; t < 8; t++) {
        int u = t & ~(M - 1);
        int o = t + u;
        float2 c0 = A[t], c1 = A[t + 8];
        float wr = CU[u], wi = (float)SGN * SU[u];
        B[o] = make_float2(c0.x + c1.x, c0.y + c1.y);
        float dr = c0.x - c1.x, di = c0.y - c1.y;
        B[o + M] = make_float2(wr*dr - wi*di, wr*di + wi*dr);
    }
}

template<int SGN>
__device__ __forceinline__ void fft16r(float2* v) {
    float2 b[16];
    fstage16<SGN, 1>(v, b);
    fstage16<SGN, 2>(b, v);
    fstage16<SGN, 4>(v, b);
    fstage16<SGN, 8>(b, v);   // result back in v
}

// ---------------------------------------------------------------------------
// 256-point FFT of one row (half-warp per row). 16x16 decomposition,
// 2 smem round trips, XOR-swizzled intermediate. Inter-radix twiddles come
// from TW[u] = e^{-2pi i u/256} (smem table, independent loads — no serial
// recurrence, no MUFU).
// ---------------------------------------------------------------------------
template<int SGN>
__device__ __forceinline__ void fft256p(float2* row, int n1, const float2* TW) {
    float2 v[16];
#pragma unroll
    for (int j = 0; j < 16; j++) v[j] = row[n1 + 16*j];
    fft16r<SGN>(v);
#pragma unroll
    for (int k2 = 1; k2 < 16; k2++) {
        float2 w = TW[(n1 * k2) & 255];
        if (SGN == 1) w.y = -w.y;
        v[k2] = cmulf(v[k2], w);
    }
    __syncwarp();
#pragma unroll
    for (int k2 = 0; k2 < 16; k2++) row[16*k2 + (n1 ^ k2)] = v[k2];
    __syncwarp();
    int k2 = n1;
    float2 u[16];
#pragma unroll
    for (int j = 0; j < 16; j++) u[j] = row[16*k2 + (j ^ k2)];
    fft16r<SGN>(u);
    __syncwarp();
#pragma unroll
    for (int k1 = 0; k1 < 16; k1++) row[k2 + 16*k1] = u[k1];
    __syncwarp();
}

// ---------------------------------------------------------------------------
// pm kernel
// ---------------------------------------------------------------------------
__global__ __launch_bounds__(256) void kpm(const float* __restrict__ hp,
                                           const float* __restrict__ b1,
                                           const float* __restrict__ W2,
                                           const float* __restrict__ b2,
                                           const float* __restrict__ W3,
                                           const float* __restrict__ b3) {
    __shared__ float smd;
    __shared__ float red[256];
    int tid = threadIdx.x;
    if (tid == 0) {
        float h1[32];
        for (int i = 0; i < 32; i++) h1[i] = fmaxf(b1[i], 0.0f);
        float md = b3[1];
        for (int j = 0; j < 16; j++) {
            float a = b2[j];
            for (int i = 0; i < 32; i++) a += h1[i] * W2[i*16 + j];
            a = fmaxf(a, 0.0f);
            md += a * W3[j*8 + 1];
        }
        smd = md;
    }
    __syncthreads();
    float md = smd;
    float acc = 0.0f;
    for (int t = tid; t < LSIG; t += 256) {
        float tf = (float)t;
        int idx = ((int)(tf * 8.0f / 65537.0f)) & 7;
        float sv = sinf(6.2831853f * tf / 65537.0f);
        float cs = hp[idx*4] + hp[idx*4+1] + hp[idx*4+2] + hp[idx*4+3];
        acc += cs * (1.0f + md * sv);
    }
    red[tid] = acc;
    __syncthreads();
    for (int st = 128; st > 0; st >>= 1) {
        if (tid < st) red[tid] += red[tid + st];
        __syncthreads();
    }
    if (tid == 0) g_pm = red[0] / (65537.0f * 4.0f);
}

// ---------------------------------------------------------------------------
// gain kernel: writes transposed gain table + bin-65536 scalar
// ---------------------------------------------------------------------------
__global__ __launch_bounds__(256) void kgain(const float* __restrict__ bw,
                                             const float* __restrict__ fw) {
    int i = blockIdx.x * 256 + threadIdx.x;
    if (i > 65536) return;
    float f  = (float)((double)i * (22050.0 / 131072.0));
    float ti = (float)i;
    float g = 1.0f;
    const float lo[6] = {1.0f, 4.0f, 8.0f, 13.0f, 30.0f, 100.0f};
    const float hi[6] = {4.0f, 8.0f, 13.0f, 30.0f, 100.0f, 200.0f};
#pragma unroll
    for (int b = 0; b < 6; b++) {
        if (f >= lo[b] && f <= hi[b]) {
            float c  = 0.5f * (lo[b] + hi[b]);
            float sg = (hi[b] - lo[b]) * 0.25f;
            float z  = (f - c) / sg;
            float m  = expf(-0.5f * z * z);
            float tm = sinf(6.2831853f * c * ti / 22050.0f);
            g *= 1.0f + m * bw[b] * (1.0f + 0.2f * tm);
        }
    }
    float pm = g_pm;
    const float sf[8] = {7.83f, 528.0f, 396.0f, 2.5f, 14.1f, 432.0f, 6.0f, 30.0f};
#pragma unroll
    for (int j = 0; j < 8; j++) {
#pragma unroll
        for (int m = 1; m <= 5; m++) {
            double hf = (double)sf[j] * (double)m;
            int hidx = (int)floor(hf * (131072.0 / 22050.0) + 0.5);
            int d = i - hidx;
            if (d >= -15 && d <= 15) {
                float win = expf(-0.5f * (float)(d*d) / 25.0f);
                float enh = fw[j] * win * powf((float)m, -1.2f) * (1.0f + pm);
                g *= 1.0f + enh;
            }
        }
    }
    if (i == 65536) g_g65536 = g;
    else g_gainT[(i & 255) * 256 + (i >> 8)] = g;
}

// ---------------------------------------------------------------------------
// Forward pass 1: 16 rows a per CTA: FFT over b of z[a+256b], * W^{ad},
// write transposed to buf1[d*256+a].
// ---------------------------------------------------------------------------
__global__ __launch_bounds__(256) void kf1(const float* __restrict__ x) {
    __shared__ float2 sA[16 * RS];
    __shared__ float2 TW[256];
    int tid = threadIdx.x;
    int s   = blockIdx.y;
    int A0  = blockIdx.x * 16;
    {
        float sv, cv;
        sincospif(-(float)tid / 128.0f, &sv, &cv);
        TW[tid] = make_float2(cv, sv);
    }
    const float* xs = x + (size_t)s * LSIG;
    for (int idx = tid; idx < 4096; idx += 256) {
        int al = idx & 15, b = idx >> 4;
        int n  = A0 + al + (b << 8);
        int i2 = 2 * n;
        float re = (i2 <= 65536) ? xs[i2] : 0.0f;
        float im = (i2 <  65536) ? xs[i2 + 1] : 0.0f;
        sA[al * RS + b] = make_float2(re, im);
    }
    __syncthreads();
    {
        int w = tid >> 5, lane = tid & 31;
        fft256p<-1>(sA + (2*w + (lane >> 4)) * RS, lane & 15, TW);
    }
    __syncthreads();
    float2* out = g_buf1 + (size_t)s * N2;
    {
        int al = tid & 15;
        int d0 = tid >> 4;            // 0..15
        int a  = A0 + al;
        float sv, cv;
        sincospif(-(float)(a * d0) / 32768.0f, &sv, &cv);
        float2 wv = make_float2(cv, sv);
        sincospif(-(float)a / 2048.0f, &sv, &cv);
        float2 wstep = make_float2(cv, sv);
#pragma unroll
        for (int it = 0; it < 16; it++) {
            int d = d0 + 16 * it;
            float2 v = sA[al * RS + d];
            out[d * 256 + a] = cmulf(v, wv);
            wv = cmulf(wv, wstep);
        }
    }
}

// ---------------------------------------------------------------------------
// FUSED middle kernel: FFT over a + spectral + IFFT over c.
// Grid (8, NSIG), 512 threads. Block Bx: central rows c0..c0+15 (c0=16Bx+1),
// halos c0-1, c0+16, and all mirror rows: 36 slots (fw 0..17, mir 18..35).
// ---------------------------------------------------------------------------
__global__ __launch_bounds__(512, 2) void kmid() {
    extern __shared__ float2 smp[];
    float2* ZS = smp;                 // 36*RSZ  (Z -> gained X -> Zi)
    float2* T  = ZS + 36*RSZ;         // 256: e^{-i pi c/256}
    float2* TW = T + 256;             // 256: e^{-2pi i u/256} (FFT table)
    float2* WR = TW + 256;            // 36:  e^{-i pi rowof(sl)/65536}
    float*  MS = (float*)(WR + 36);   // 36*MSS magnitudes
    float*  SC = MS + 36*MSS;         // [2] = |X[65536]|

    const int tid = threadIdx.x;
    const int sig = blockIdx.y;
    const int Bx  = blockIdx.x;
    const int c0  = NC*Bx + 1;
    const float inv = 1.0f / 65536.0f;

    auto rowof = [&](int sl) -> int {
        return (sl < NSL) ? ((c0 - 1 + sl) & 255) : ((257 - c0 - (sl - NSL)) & 255);
    };

    const float2* in = g_buf1 + (size_t)sig * N2;

    // tables
    if (tid < 256) {
        float sv, cv;
        sincospif(-(float)tid / 256.0f, &sv, &cv);
        T[tid] = make_float2(cv, sv);
    } else {
        int u = tid - 256;
        float sv, cv;
        sincospif(-(float)u / 128.0f, &sv, &cv);
        TW[u] = make_float2(cv, sv);
    }
    if (tid < 36) {
        float sv, cv;
        sincospif(-(float)rowof(tid) / 65536.0f, &sv, &cv);
        WR[tid] = make_float2(cv, sv);
    }
    // load 36 rows
    for (int idx = tid; idx < 36*256; idx += 512) {
        int sl = idx >> 8, c = idx & 255;
        ZS[sl*RSZ + c] = in[rowof(sl)*256 + c];
    }
    __syncthreads();

    // phase 1: forward FFT over cols for 36 rows
    {
        int w = tid >> 5, lane = tid & 31, n1 = lane & 15;
        int hw = 2*w + (lane >> 4);
        fft256p<-1>(ZS + hw*RSZ, n1, TW);
        if (hw < 4) fft256p<-1>(ZS + (32 + hw)*RSZ, n1, TW);
    }
    __syncthreads();

    // phase 2: pair-owned gained X + magnitudes, in place.
#pragma unroll
    for (int t = tid; t < NSL*256; t += 512) {
        int sl = t >> 8, c = t & 255;
        int r  = rowof(sl);
        int ps = sl + NSL;
        int cm = (r == 0) ? ((256 - c) & 255) : (255 - c);
        if (r == 0 && c == 0) {
            float2 z0 = ZS[0];
            float X0 = (z0.x + z0.y) * g_gainT[0];
            float XN = (z0.x - z0.y) * g_g65536;
            ZS[sl*RSZ]    = make_float2(X0, 0.f);
            ZS[ps*RSZ]    = make_float2(XN, 0.f);
            MS[sl*MSS]    = fabsf(X0);
            MS[ps*MSS]    = fabsf(XN);
            SC[2] = fabsf(XN);
            continue;
        }
        float2 zj = ZS[sl*RSZ + c];
        float2 zm = ZS[ps*RSZ + cm];
        float Er = 0.5f*(zj.x + zm.x), Ei = 0.5f*(zj.y - zm.y);
        float Or = 0.5f*(zj.y + zm.y), Oi = -0.5f*(zj.x - zm.x);
        float2 W = cmulf(WR[sl], T[c]);
        float wor = W.x*Or - W.y*Oi, woi = W.x*Oi + W.y*Or;
        int rm = (256 - r) & 255;
        float gp = g_gainT[(r  << 8) + c];
        float gm = g_gainT[(rm << 8) + cm];
        float XPr = gp*(Er + wor), XPi = gp*(Ei + woi);
        float XMr = gm*(Er - wor), XMi = -gm*(Ei - woi);   // conj applied
        ZS[sl*RSZ + c]  = make_float2(XPr, XPi);
        ZS[ps*RSZ + cm] = make_float2(XMr, XMi);
        MS[sl*MSS + c]  = sqrtf(XPr*XPr + XPi*XPi);
        MS[ps*MSS + cm] = sqrtf(XMr*XMr + XMi*XMi);
    }
    __syncthreads();

    // phase 3: smooth-rescale + c2r combine, write both Zi in place.
#pragma unroll
    for (int t = tid; t < NC*256; t += 512) {
        int st = (t >> 8) + 1;        // 1..16 (central rows)
        int c  = t & 255;
        int ps = st + NSL;
        int cm = 255 - c;
        float2 a0 = ZS[st*RSZ + c];
        float2 b0 = ZS[ps*RSZ + cm];
        float magP = MS[st*MSS + c];
        float magM = MS[ps*MSS + cm];
        float msP = 0.7f*magP + 0.15f*MS[(st-1)*MSS + c] + 0.15f*MS[(st+1)*MSS + c];
        float nbM;                     // mag at jm+1
        if (Bx == 0 && st == 1)
            nbM = (c == 0) ? SC[2] : MS[(256 - c)];           // row 0, col 256-c
        else
            nbM = MS[(ps-1)*MSS + cm];
        float msM = 0.7f*magM + 0.15f*nbM + 0.15f*MS[(ps+1)*MSS + cm];
        float2 a, b;
        if (magP > 0.f) { float rr = msP / magP; a = make_float2(a0.x*rr, a0.y*rr); }
        else a = make_float2(msP, 0.f);
        if (magM > 0.f) { float rr = msM / magM; b = make_float2(b0.x*rr, b0.y*rr); }
        else b = make_float2(msM, 0.f);
        float2 W = cmulf(WR[st], T[c]);
        float er = 0.5f*(a.x + b.x);
        float ei = 0.5f*(a.y - b.y);
        float dr = 0.5f*(a.x - b.x);
        float di = 0.5f*(a.y + b.y);
        float orr = W.x*dr + W.y*di;
        float oi  = W.x*di - W.y*dr;
        ZS[st*RSZ + c]  = make_float2((er - oi)*inv, (ei + orr)*inv);
        ZS[ps*RSZ + cm] = make_float2((er + oi)*inv, (orr - ei)*inv);
    }
    if (Bx == 0 && tid < 256) {
        int c = tid;
        if (c == 0) {
            float X0 = ZS[0].x;
            float XN = ZS[NSL*RSZ].x;
            ZS[0] = make_float2(0.5f*(X0 + XN)*inv, 0.5f*(X0 - XN)*inv);
        } else {
            float2 a0 = ZS[c];                            // row 0, bin 256c
            float2 b0 = ZS[NSL*RSZ + (256 - c)];          // bin 65536-256c
            float magP = MS[c];
            float magM = MS[NSL*MSS + (256 - c)];
            float msP = 0.7f*magP + 0.15f*MS[(NSL+1)*MSS + (c-1)] + 0.15f*MS[MSS + c];
            float msM = 0.7f*magM + 0.15f*MS[(NSL+1)*MSS + (255 - c)] + 0.15f*MS[MSS + (256 - c)];
            float2 a, b;
            if (magP > 0.f) { float rr = msP / magP; a = make_float2(a0.x*rr, a0.y*rr); }
            else a = make_float2(msP, 0.f);
            if (magM > 0.f) { float rr = msM / magM; b = make_float2(b0.x*rr, b0.y*rr); }
            else b = make_float2(msM, 0.f);
            float2 W = T[c];
            float er = 0.5f*(a.x + b.x);
            float ei = 0.5f*(a.y - b.y);
            float dr = 0.5f*(a.x - b.x);
            float di = 0.5f*(a.y + b.y);
            float orr = W.x*dr + W.y*di;
            float oi  = W.x*di - W.y*dr;
            ZS[c] = make_float2((er - oi)*inv, (ei + orr)*inv);
        }
    }
    __syncthreads();

    // phase 4: inverse FFT over c (slots 1..16, 19..34; block 0 also slot 0)
    {
        int w = tid >> 5, lane = tid & 31, n1 = lane & 15;
        int hw = 2*w + (lane >> 4);                  // 0..31
        int sl = (hw < 16) ? (hw + 1) : (hw + 3);    // 1..16, 19..34
        fft256p<1>(ZS + sl*RSZ, n1, TW);
        if (Bx == 0 && w == 0) fft256p<1>(ZS, n1, TW);   // slot 0 (dup halves, benign)
    }
    __syncthreads();

    // phase 5: twiddle * e^{+2pi i d a/65536}, write buf2[a*256+d]
    float2* out = g_buf2 + (size_t)sig * N2;
    {
        int rr = tid >> 4;             // 0..31
        int a0 = tid & 15;             // 0..15
        int g  = rr >> 4, rl = rr & 15;
        int sl, d;
        if (g == 0) { sl = 1 + rl;        d = c0 + rl; }
        else        { sl = NSL + 1 + rl;  d = (256 - c0 - rl) & 255; }
        float sv, cv;
        sincospif((float)(d * a0) / 32768.0f, &sv, &cv);
        float2 wv = make_float2(cv, sv);
        sincospif((float)d / 2048.0f, &sv, &cv);
        float2 wstep = make_float2(cv, sv);
#pragma unroll
        for (int it = 0; it < 16; it++) {
            int a = a0 + 16*it;
            float2 v = ZS[sl*RSZ + a];
            out[a * 256 + d] = cmulf(v, wv);
            wv = cmulf(wv, wstep);
        }
    }
    if (Bx == 0 && tid < 256) {
        out[tid * 256 + 0] = ZS[tid];   // row 0, twiddle = 1
    }
}

// ---------------------------------------------------------------------------
// Inverse pass 2: 16 rows a per CTA: IFFT over d -> z[a+256b]; write y.
// ---------------------------------------------------------------------------
__global__ __launch_bounds__(256) void ki2(float* __restrict__ y) {
    __shared__ float2 sA[16 * RS];
    __shared__ float2 TW[256];
    int tid = threadIdx.x;
    int s   = blockIdx.y;
    int A0  = blockIdx.x * 16;
    {
        float sv, cv;
        sincospif(-(float)tid / 128.0f, &sv, &cv);
        TW[tid] = make_float2(cv, sv);
    }
    const float2* in = g_buf2 + (size_t)s * N2;
    for (int idx = tid; idx < 4096; idx += 256) {
        int row = idx >> 8, col = idx & 255;
        sA[row * RS + col] = in[(A0 + row) * 256 + col];
    }
    __syncthreads();
    {
        int w = tid >> 5, lane = tid & 31;
        fft256p<1>(sA + (2*w + (lane >> 4)) * RS, lane & 15, TW);
    }
    __syncthreads();
    float* ys = y + (size_t)s * LSIG;
    for (int idx = tid; idx < 4096; idx += 256) {
        int al = idx & 15, b = idx >> 4;
        int n  = A0 + al + (b << 8);
        int i2 = 2 * n;
        float2 v = sA[al * RS + b];
        if (i2 <= 65536) ys[i2] = v.x;
        if (i2 <  65536) ys[i2 + 1] = v.y;
    }
}

// ---------------------------------------------------------------------------
extern "C" void kernel_launch(void* const* d_in, const int* in_sizes, int n_in,
                              void* d_out, int out_size) {
    const float* x  = (const float*)d_in[0];
    const float* bw = (const float*)d_in[1];
    const float* fw = (const float*)d_in[2];
    const float* hp = (const float*)d_in[3];
    const float* b1 = (const float*)d_in[5];
    const float* W2 = (const float*)d_in[6];
    const float* b2 = (const float*)d_in[7];
    const float* W3 = (const float*)d_in[8];
    const float* b3 = (const float*)d_in[9];
    float* y = (float*)d_out;

    const int KMID_SMEM = (36*RSZ + 256 + 256 + 36) * (int)sizeof(float2)
                        + (36*MSS + 4) * (int)sizeof(float);
    cudaFuncSetAttribute(kmid, cudaFuncAttributeMaxDynamicSharedMemorySize, KMID_SMEM);

    kpm<<<1, 256>>>(hp, b1, W2, b2, W3, b3);
    kgain<<<257, 256>>>(bw, fw);
    kf1<<<dim3(16, NSIG), 256>>>(x);
    kmid<<<dim3(8, NSIG), 512, KMID_SMEM>>>();
    ki2<<<dim3(16, NSIG), 256>>>(y);
}

// round 10
// speedup vs baseline: 1.0537x; 1.0537x over previous
#include <cuda_runtime.h>
#include <math.h>

// Problem constants
#define NSIG 256          // B*C = 128*2 signals
#define LSIG 65537        // signal length (== RLEN)
#define N2   65536        // packed complex FFT length (NFFT/2)
#define RS   257          // smem row stride in float2 (kf1/ki2)
#define RSZ  257          // smem row stride in float2 (kmid)

// Scratch (allowed: __device__ globals, no allocation)
__device__ float2 g_buf1[(size_t)NSIG * N2];   // 134 MB
__device__ float2 g_buf2[(size_t)NSIG * N2];   // 134 MB
__device__ float  g_gainT[65536];              // gain transposed: [r*256+c] = gain[r+256c]
__device__ float  g_g65536;                    // gain at bin 65536
__device__ float  g_pm;

__device__ __forceinline__ float2 cmulf(float2 a, float2 b) {
    return make_float2(a.x*b.x - a.y*b.y, a.x*b.y + a.y*b.x);
}

// ---------------------------------------------------------------------------
// Register-resident 16-point FFT (Stockham radix-2, natural order in/out).
// ---------------------------------------------------------------------------
template<int SGN, int M>
__device__ __forceinline__ void fstage16(const float2* A, float2* B) {
    const float CU[8] = {1.f, 0.92387953251f, 0.70710678119f, 0.38268343236f,
                         0.f, -0.38268343236f, -0.70710678119f, -0.92387953251f};
    const float SU[8] = {0.f, 0.38268343236f, 0.70710678119f, 0.92387953251f,
                         1.f, 0.92387953251f, 0.70710678119f, 0.38268343236f};
#pragma unroll
    for (int t = 0; t < 8; t++) {
        int u = t & ~(M - 1);
        int o = t + u;
        float2 c0 = A[t], c1 = A[t + 8];
        float wr = CU[u], wi = (float)SGN * SU[u];
        B[o] = make_float2(c0.x + c1.x, c0.y + c1.y);
        float dr = c0.x - c1.x, di = c0.y - c1.y;
        B[o + M] = make_float2(wr*dr - wi*di, wr*di + wi*dr);
    }
}

template<int SGN>
__device__ __forceinline__ void fft16r(float2* v) {
    float2 b[16];
    fstage16<SGN, 1>(v, b);
    fstage16<SGN, 2>(b, v);
    fstage16<SGN, 4>(v, b);
    fstage16<SGN, 8>(b, v);   // result back in v
}

// ---------------------------------------------------------------------------
// 256-point FFT of one row (half-warp per row; two rows share one warp).
// 16x16 decomposition, 2 smem round trips, XOR-swizzled intermediate.
// Inter-radix twiddles via 4 independent stepped chains (dep depth ~5, not 15).
// ---------------------------------------------------------------------------
template<int SGN>
__device__ __forceinline__ void fft256p(float2* row, int n1) {
    float2 v[16];
#pragma unroll
    for (int j = 0; j < 16; j++) v[j] = row[n1 + 16*j];
    fft16r<SGN>(v);
    float si, co;
    sincospif((float)SGN * (float)n1 * (1.0f/128.0f), &si, &co);
    float2 w1 = make_float2(co, si);                 // W256^{SGN*n1}
    float2 w2 = cmulf(w1, w1);
    float2 w3 = cmulf(w2, w1);
    float2 w4 = cmulf(w2, w2);
    v[1] = cmulf(v[1], w1);
    v[2] = cmulf(v[2], w2);
    v[3] = cmulf(v[3], w3);
    v[4] = cmulf(v[4], w4);
    float2 a1 = cmulf(w1, w4), a2 = cmulf(w2, w4), a3 = cmulf(w3, w4), a4 = cmulf(w4, w4);
    v[5] = cmulf(v[5], a1);
    v[6] = cmulf(v[6], a2);
    v[7] = cmulf(v[7], a3);
    v[8] = cmulf(v[8], a4);
    a1 = cmulf(a1, w4); a2 = cmulf(a2, w4); a3 = cmulf(a3, w4); a4 = cmulf(a4, w4);
    v[9]  = cmulf(v[9],  a1);
    v[10] = cmulf(v[10], a2);
    v[11] = cmulf(v[11], a3);
    v[12] = cmulf(v[12], a4);
    a1 = cmulf(a1, w4); a2 = cmulf(a2, w4); a3 = cmulf(a3, w4);
    v[13] = cmulf(v[13], a1);
    v[14] = cmulf(v[14], a2);
    v[15] = cmulf(v[15], a3);
    __syncwarp();
#pragma unroll
    for (int k2 = 0; k2 < 16; k2++) row[16*k2 + (n1 ^ k2)] = v[k2];
    __syncwarp();
    int k2 = n1;
    float2 u[16];
#pragma unroll
    for (int j = 0; j < 16; j++) u[j] = row[16*k2 + (j ^ k2)];
    fft16r<SGN>(u);
    __syncwarp();
#pragma unroll
    for (int k1 = 0; k1 < 16; k1++) row[k2 + 16*k1] = u[k1];
    __syncwarp();
}

// ---------------------------------------------------------------------------
// pm kernel
// ---------------------------------------------------------------------------
__global__ __launch_bounds__(256) void kpm(const float* __restrict__ hp,
                                           const float* __restrict__ b1,
                                           const float* __restrict__ W2,
                                           const float* __restrict__ b2,
                                           const float* __restrict__ W3,
                                           const float* __restrict__ b3) {
    __shared__ float smd;
    __shared__ float red[256];
    int tid = threadIdx.x;
    if (tid == 0) {
        float h1[32];
        for (int i = 0; i < 32; i++) h1[i] = fmaxf(b1[i], 0.0f);
        float md = b3[1];
        for (int j = 0; j < 16; j++) {
            float a = b2[j];
            for (int i = 0; i < 32; i++) a += h1[i] * W2[i*16 + j];
            a = fmaxf(a, 0.0f);
            md += a * W3[j*8 + 1];
        }
        smd = md;
    }
    __syncthreads();
    float md = smd;
    float acc = 0.0f;
    for (int t = tid; t < LSIG; t += 256) {
        float tf = (float)t;
        int idx = ((int)(tf * 8.0f / 65537.0f)) & 7;
        float sv = sinf(6.2831853f * tf / 65537.0f);
        float cs = hp[idx*4] + hp[idx*4+1] + hp[idx*4+2] + hp[idx*4+3];
        acc += cs * (1.0f + md * sv);
    }
    red[tid] = acc;
    __syncthreads();
    for (int st = 128; st > 0; st >>= 1) {
        if (tid < st) red[tid] += red[tid + st];
        __syncthreads();
    }
    if (tid == 0) g_pm = red[0] / (65537.0f * 4.0f);
}

// ---------------------------------------------------------------------------
// gain kernel: writes transposed gain table + bin-65536 scalar
// ---------------------------------------------------------------------------
__global__ __launch_bounds__(256) void kgain(const float* __restrict__ bw,
                                             const float* __restrict__ fw) {
    int i = blockIdx.x * 256 + threadIdx.x;
    if (i > 65536) return;
    float f  = (float)((double)i * (22050.0 / 131072.0));
    float ti = (float)i;
    float g = 1.0f;
    const float lo[6] = {1.0f, 4.0f, 8.0f, 13.0f, 30.0f, 100.0f};
    const float hi[6] = {4.0f, 8.0f, 13.0f, 30.0f, 100.0f, 200.0f};
#pragma unroll
    for (int b = 0; b < 6; b++) {
        if (f >= lo[b] && f <= hi[b]) {
            float c  = 0.5f * (lo[b] + hi[b]);
            float sg = (hi[b] - lo[b]) * 0.25f;
            float z  = (f - c) / sg;
            float m  = expf(-0.5f * z * z);
            float tm = sinf(6.2831853f * c * ti / 22050.0f);
            g *= 1.0f + m * bw[b] * (1.0f + 0.2f * tm);
        }
    }
    float pm = g_pm;
    const float sf[8] = {7.83f, 528.0f, 396.0f, 2.5f, 14.1f, 432.0f, 6.0f, 30.0f};
#pragma unroll
    for (int j = 0; j < 8; j++) {
#pragma unroll
        for (int m = 1; m <= 5; m++) {
            double hf = (double)sf[j] * (double)m;
            int hidx = (int)floor(hf * (131072.0 / 22050.0) + 0.5);
            int d = i - hidx;
            if (d >= -15 && d <= 15) {
                float win = expf(-0.5f * (float)(d*d) / 25.0f);
                float enh = fw[j] * win * powf((float)m, -1.2f) * (1.0f + pm);
                g *= 1.0f + enh;
            }
        }
    }
    if (i == 65536) g_g65536 = g;
    else g_gainT[(i & 255) * 256 + (i >> 8)] = g;
}

// ---------------------------------------------------------------------------
// Forward pass 1: 16 rows a per CTA: FFT over b of z[a+256b], * W^{ad},
// write transposed to buf1[d*256+a]. Output twiddles: 4 stepped chains.
// ---------------------------------------------------------------------------
__global__ __launch_bounds__(256) void kf1(const float* __restrict__ x) {
    __shared__ float2 sA[16 * RS];
    int tid = threadIdx.x;
    int s   = blockIdx.y;
    int A0  = blockIdx.x * 16;
    const float* xs = x + (size_t)s * LSIG;
    for (int idx = tid; idx < 4096; idx += 256) {
        int al = idx & 15, b = idx >> 4;
        int n  = A0 + al + (b << 8);
        int i2 = 2 * n;
        float re = (i2 <= 65536) ? xs[i2] : 0.0f;
        float im = (i2 <  65536) ? xs[i2 + 1] : 0.0f;
        sA[al * RS + b] = make_float2(re, im);
    }
    __syncthreads();
    {
        int w = tid >> 5, lane = tid & 31;
        fft256p<-1>(sA + (2*w + (lane >> 4)) * RS, lane & 15);
    }
    __syncthreads();
    float2* out = g_buf1 + (size_t)s * N2;
    {
        int al = tid & 15;
        int d0 = tid >> 4;            // 0..15
        int a  = A0 + al;
        float sv, cv;
        sincospif(-(float)(a * d0) / 32768.0f, &sv, &cv);
        float2 wv = make_float2(cv, sv);              // W^(a*d0)
        sincospif(-(float)a / 2048.0f, &sv, &cv);
        float2 ws = make_float2(cv, sv);              // W^(16a)
        float2 ws2 = cmulf(ws, ws);
        float2 ws4 = cmulf(ws2, ws2);
        float2 q0 = wv;
        float2 q1 = cmulf(wv, ws);
        float2 q2 = cmulf(wv, ws2);
        float2 q3 = cmulf(q1, ws2);
#pragma unroll
        for (int g4 = 0; g4 < 4; g4++) {
            int d = d0 + 64*g4;
            out[(d     ) * 256 + a] = cmulf(sA[al*RS + d     ], q0);
            out[(d + 16) * 256 + a] = cmulf(sA[al*RS + d + 16], q1);
            out[(d + 32) * 256 + a] = cmulf(sA[al*RS + d + 32], q2);
            out[(d + 48) * 256 + a] = cmulf(sA[al*RS + d + 48], q3);
            if (g4 < 3) {
                q0 = cmulf(q0, ws4); q1 = cmulf(q1, ws4);
                q2 = cmulf(q2, ws4); q3 = cmulf(q3, ws4);
            }
        }
    }
}

// ---------------------------------------------------------------------------
// FUSED middle kernel: kf2 (FFT over a) + spectral + ki1 (IFFT over c).
// Grid (16, NSIG), 512 threads. Block Bx: central rows c0..c0+7 (c0=8Bx+1),
// halos c0-1, c0+8, and all their mirror rows (20 slots).
// ---------------------------------------------------------------------------
__global__ __launch_bounds__(512, 2) void kmid() {
    extern __shared__ float2 smp[];
    float2* ZS = smp;                 // 20*RSZ  (Z -> gained X -> Zi)
    float2* T  = ZS + 20*RSZ;         // 256: e^{-i pi c/256}
    float2* WR = T + 256;             // 20:  e^{-i pi rowof(sl)/65536}
    float*  MS = (float*)(WR + 20);   // 20*260 magnitudes
    float*  SC = MS + 20*260;         // [2] = |X[65536]|

    const int tid = threadIdx.x;
    const int sig = blockIdx.y;
    const int Bx  = blockIdx.x;
    const int c0  = 8*Bx + 1;
    const float inv = 1.0f / 65536.0f;

    auto rowof = [&](int sl) -> int {
        return (sl < 10) ? ((c0 - 1 + sl) & 255) : ((257 - c0 - (sl - 10)) & 255);
    };

    const float2* in = g_buf1 + (size_t)sig * N2;

    // tables
    if (tid < 256) {
        float sv, cv;
        sincospif(-(float)tid / 256.0f, &sv, &cv);
        T[tid] = make_float2(cv, sv);
    } else if (tid < 276) {
        int sl = tid - 256;
        float sv, cv;
        sincospif(-(float)rowof(sl) / 65536.0f, &sv, &cv);
        WR[sl] = make_float2(cv, sv);
    }
    // load 20 rows
    for (int idx = tid; idx < 20*256; idx += 512) {
        int sl = idx >> 8, c = idx & 255;
        ZS[sl*RSZ + c] = in[rowof(sl)*256 + c];
    }
    __syncthreads();

    // phase 1: forward FFT over cols for 20 rows
    {
        int w = tid >> 5, lane = tid & 31;
        if (w < 10) fft256p<-1>(ZS + (2*w + (lane >> 4))*RSZ, lane & 15);
    }
    __syncthreads();

    // phase 2: pair-owned gained X + magnitudes, in place.
#pragma unroll
    for (int t = tid; t < 2560; t += 512) {
        int st = t >> 8, c = t & 255;
        int r  = rowof(st);
        int ps = st + 10;
        int cm = (r == 0) ? ((256 - c) & 255) : (255 - c);
        if (r == 0 && c == 0) {
            float2 z0 = ZS[0];
            float X0 = (z0.x + z0.y) * g_gainT[0];
            float XN = (z0.x - z0.y) * g_g65536;
            ZS[st*RSZ]    = make_float2(X0, 0.f);
            ZS[ps*RSZ]    = make_float2(XN, 0.f);
            MS[st*260]    = fabsf(X0);
            MS[ps*260]    = fabsf(XN);
            SC[2] = fabsf(XN);
            continue;
        }
        float2 zj = ZS[st*RSZ + c];
        float2 zm = ZS[ps*RSZ + cm];
        float Er = 0.5f*(zj.x + zm.x), Ei = 0.5f*(zj.y - zm.y);
        float Or = 0.5f*(zj.y + zm.y), Oi = -0.5f*(zj.x - zm.x);
        float2 W = cmulf(WR[st], T[c]);
        float wor = W.x*Or - W.y*Oi, woi = W.x*Oi + W.y*Or;
        int rm = (256 - r) & 255;
        float gp = g_gainT[(r  << 8) + c];
        float gm = g_gainT[(rm << 8) + cm];
        float XPr = gp*(Er + wor), XPi = gp*(Ei + woi);
        float XMr = gm*(Er - wor), XMi = -gm*(Ei - woi);   // conj applied
        ZS[st*RSZ + c]  = make_float2(XPr, XPi);
        ZS[ps*RSZ + cm] = make_float2(XMr, XMi);
        MS[st*260 + c]  = sqrtf(XPr*XPr + XPi*XPi);
        MS[ps*260 + cm] = sqrtf(XMr*XMr + XMi*XMi);
    }
    __syncthreads();

    // phase 3: smooth-rescale + c2r combine, write both Zi in place.
#pragma unroll
    for (int t = tid; t < 2048; t += 512) {
        int st = (t >> 8) + 1;        // 1..8 (central rows)
        int c  = t & 255;
        int ps = st + 10;
        int cm = 255 - c;
        float2 a0 = ZS[st*RSZ + c];
        float2 b0 = ZS[ps*RSZ + cm];
        float magP = MS[st*260 + c];
        float magM = MS[ps*260 + cm];
        float msP = 0.7f*magP + 0.15f*MS[(st-1)*260 + c] + 0.15f*MS[(st+1)*260 + c];
        float nbM;                     // mag at jm+1
        if (Bx == 0 && st == 1)
            nbM = (c == 0) ? SC[2] : MS[(256 - c)];           // row 0, col 256-c
        else
            nbM = MS[(ps-1)*260 + cm];
        float msM = 0.7f*magM + 0.15f*nbM + 0.15f*MS[(ps+1)*260 + cm];
        float2 a, b;
        if (magP > 0.f) { float rr = msP / magP; a = make_float2(a0.x*rr, a0.y*rr); }
        else a = make_float2(msP, 0.f);
        if (magM > 0.f) { float rr = msM / magM; b = make_float2(b0.x*rr, b0.y*rr); }
        else b = make_float2(msM, 0.f);
        float2 W = cmulf(WR[st], T[c]);
        float er = 0.5f*(a.x + b.x);
        float ei = 0.5f*(a.y - b.y);
        float dr = 0.5f*(a.x - b.x);
        float di = 0.5f*(a.y + b.y);
        float orr = W.x*dr + W.y*di;
        float oi  = W.x*di - W.y*dr;
        ZS[st*RSZ + c]  = make_float2((er - oi)*inv, (ei + orr)*inv);
        ZS[ps*RSZ + cm] = make_float2((er + oi)*inv, (orr - ei)*inv);
    }
    if (Bx == 0 && tid < 256) {
        int c = tid;
        if (c == 0) {
            float X0 = ZS[0].x;
            float XN = ZS[10*RSZ].x;
            ZS[0] = make_float2(0.5f*(X0 + XN)*inv, 0.5f*(X0 - XN)*inv);
        } else {
            float2 a0 = ZS[c];                       // row 0, bin 256c
            float2 b0 = ZS[10*RSZ + (256 - c)];      // bin 65536-256c
            float magP = MS[c];
            float magM = MS[10*260 + (256 - c)];
            float msP = 0.7f*magP + 0.15f*MS[11*260 + (c-1)] + 0.15f*MS[260 + c];
            float msM = 0.7f*magM + 0.15f*MS[11*260 + (255 - c)] + 0.15f*MS[260 + (256 - c)];
            float2 a, b;
            if (magP > 0.f) { float rr = msP / magP; a = make_float2(a0.x*rr, a0.y*rr); }
            else a = make_float2(msP, 0.f);
            if (magM > 0.f) { float rr = msM / magM; b = make_float2(b0.x*rr, b0.y*rr); }
            else b = make_float2(msM, 0.f);
            float2 W = T[c];
            float er = 0.5f*(a.x + b.x);
            float ei = 0.5f*(a.y - b.y);
            float dr = 0.5f*(a.x - b.x);
            float di = 0.5f*(a.y + b.y);
            float orr = W.x*dr + W.y*di;
            float oi  = W.x*di - W.y*dr;
            ZS[c] = make_float2((er - oi)*inv, (ei + orr)*inv);
        }
    }
    __syncthreads();

    // phase 4: inverse FFT over c for output rows (slots 1..8, 11..18, +0)
    {
        int w = tid >> 5, lane = tid & 31;
        if (w < 8) {
            int hw = 2*w + (lane >> 4);                  // 0..15
            int sl = (hw < 8) ? (1 + hw) : (3 + hw);     // 1..8, 11..18
            fft256p<1>(ZS + sl*RSZ, lane & 15);
        } else if (w == 8 && Bx == 0) {
            fft256p<1>(ZS, lane & 15);                   // slot 0 (dup half-warps)
        }
    }
    __syncthreads();

    // phase 5: twiddle * e^{+2pi i d a/65536}, write buf2[a*256+d] (2 chains)
    float2* out = g_buf2 + (size_t)sig * N2;
    {
        int g  = tid >> 8;
        int rl = tid & 7;
        int a0 = (tid & 255) >> 3;     // 0..31
        int sl, d;
        if (g == 0) { sl = 1 + rl;  d = c0 + rl; }
        else        { sl = 18 - rl; d = 249 - c0 + rl; }
        float sv, cv;
        sincospif((float)(d * a0) / 32768.0f, &sv, &cv);
        float2 wv = make_float2(cv, sv);
        sincospif((float)d / 1024.0f, &sv, &cv);
        float2 ws = make_float2(cv, sv);              // W^{-32d} dir + : e^{+2pi i 32 d/65536}
        float2 ws2 = cmulf(ws, ws);
        float2 q0 = wv;
        float2 q1 = cmulf(wv, ws);
#pragma unroll
        for (int g2 = 0; g2 < 4; g2++) {
            int a = a0 + 64*g2;
            out[(a     ) * 256 + d] = cmulf(ZS[sl*RSZ + a     ], q0);
            out[(a + 32) * 256 + d] = cmulf(ZS[sl*RSZ + a + 32], q1);
            if (g2 < 3) { q0 = cmulf(q0, ws2); q1 = cmulf(q1, ws2); }
        }
    }
    if (Bx == 0 && tid < 256) {
        out[tid * 256 + 0] = ZS[tid];   // row 0, twiddle = 1
    }
}

// ---------------------------------------------------------------------------
// Inverse pass 2: 16 rows a per CTA: IFFT over d -> z[a+256b]; write y.
// ---------------------------------------------------------------------------
__global__ __launch_bounds__(256) void ki2(float* __restrict__ y) {
    __shared__ float2 sA[16 * RS];
    int tid = threadIdx.x;
    int s   = blockIdx.y;
    int A0  = blockIdx.x * 16;
    const float2* in = g_buf2 + (size_t)s * N2;
    for (int idx = tid; idx < 4096; idx += 256) {
        int row = idx >> 8, col = idx & 255;
        sA[row * RS + col] = in[(A0 + row) * 256 + col];
    }
    __syncthreads();
    {
        int w = tid >> 5, lane = tid & 31;
        fft256p<1>(sA + (2*w + (lane >> 4)) * RS, lane & 15);
    }
    __syncthreads();
    float* ys = y + (size_t)s * LSIG;
    for (int idx = tid; idx < 4096; idx += 256) {
        int al = idx & 15, b = idx >> 4;
        int n  = A0 + al + (b << 8);
        int i2 = 2 * n;
        float2 v = sA[al * RS + b];
        if (i2 <= 65536) ys[i2] = v.x;
        if (i2 <  65536) ys[i2 + 1] = v.y;
    }
}

// ---------------------------------------------------------------------------
extern "C" void kernel_launch(void* const* d_in, const int* in_sizes, int n_in,
                              void* d_out, int out_size) {
    const float* x  = (const float*)d_in[0];
    const float* bw = (const float*)d_in[1];
    const float* fw = (const float*)d_in[2];
    const float* hp = (const float*)d_in[3];
    const float* b1 = (const float*)d_in[5];
    const float* W2 = (const float*)d_in[6];
    const float* b2 = (const float*)d_in[7];
    const float* W3 = (const float*)d_in[8];
    const float* b3 = (const float*)d_in[9];
    float* y = (float*)d_out;

    const int KMID_SMEM = (20*RSZ + 256 + 20) * (int)sizeof(float2)
                        + (20*260 + 4) * (int)sizeof(float);
    cudaFuncSetAttribute(kmid, cudaFuncAttributeMaxDynamicSharedMemorySize, KMID_SMEM);

    kpm<<<1, 256>>>(hp, b1, W2, b2, W3, b3);
    kgain<<<257, 256>>>(bw, fw);
    kf1<<<dim3(16, NSIG), 256>>>(x);
    kmid<<<dim3(16, NSIG), 512, KMID_SMEM>>>();
    ki2<<<dim3(16, NSIG), 256>>>(y);
}

// round 11
// speedup vs baseline: 1.2754x; 1.2104x over previous
#include <cuda_runtime.h>
#include <math.h>

// Problem constants
#define NSIG 256          // B*C = 128*2 signals
#define LSIG 65537        // signal length (== RLEN)
#define N2   65536        // packed complex FFT length (NFFT/2)
#define RS   257          // smem row stride in float2 (kf1/ki2)
#define RSZ  257          // smem row stride in float2 (kmid)

// Scratch (allowed: __device__ globals, no allocation)
__device__ __align__(16) float2 g_buf1[(size_t)NSIG * N2];   // 134 MB
__device__ __align__(16) float2 g_buf2[(size_t)NSIG * N2];   // 134 MB
__device__ float  g_gainT[65536];              // gain transposed: [r*256+c] = gain[r+256c]
__device__ float  g_g65536;                    // gain at bin 65536
__device__ float  g_pm;

__device__ __forceinline__ float2 cmulf(float2 a, float2 b) {
    return make_float2(a.x*b.x - a.y*b.y, a.x*b.y + a.y*b.x);
}

// ---------------------------------------------------------------------------
// Register-resident 16-point FFT (Stockham radix-2, natural order in/out).
// ---------------------------------------------------------------------------
template<int SGN, int M>
__device__ __forceinline__ void fstage16(const float2* A, float2* B) {
    const float CU[8] = {1.f, 0.92387953251f, 0.70710678119f, 0.38268343236f,
                         0.f, -0.38268343236f, -0.70710678119f, -0.92387953251f};
    const float SU[8] = {0.f, 0.38268343236f, 0.70710678119f, 0.92387953251f,
                         1.f, 0.92387953251f, 0.70710678119f, 0.38268343236f};
#pragma unroll
    for (int t = 0; t < 8; t++) {
        int u = t & ~(M - 1);
        int o = t + u;
        float2 c0 = A[t], c1 = A[t + 8];
        float wr = CU[u], wi = (float)SGN * SU[u];
        B[o] = make_float2(c0.x + c1.x, c0.y + c1.y);
        float dr = c0.x - c1.x, di = c0.y - c1.y;
        B[o + M] = make_float2(wr*dr - wi*di, wr*di + wi*dr);
    }
}

template<int SGN>
__device__ __forceinline__ void fft16r(float2* v) {
    float2 b[16];
    fstage16<SGN, 1>(v, b);
    fstage16<SGN, 2>(b, v);
    fstage16<SGN, 4>(v, b);
    fstage16<SGN, 8>(b, v);   // result back in v
}

// ---------------------------------------------------------------------------
// 256-point FFT of one row (half-warp per row; two rows share one warp).
// 16x16 decomposition, 2 smem round trips, XOR-swizzled intermediate.
// ---------------------------------------------------------------------------
template<int SGN>
__device__ __forceinline__ void fft256p(float2* row, int n1) {
    float2 v[16];
#pragma unroll
    for (int j = 0; j < 16; j++) v[j] = row[n1 + 16*j];
    fft16r<SGN>(v);
    float si, co;
    sincospif((float)SGN * (float)n1 * (1.0f/128.0f), &si, &co);
    float2 w1 = make_float2(co, si);
    float2 wv = w1;
#pragma unroll
    for (int k2 = 1; k2 < 16; k2++) { v[k2] = cmulf(v[k2], wv); wv = cmulf(wv, w1); }
    __syncwarp();
#pragma unroll
    for (int k2 = 0; k2 < 16; k2++) row[16*k2 + (n1 ^ k2)] = v[k2];
    __syncwarp();
    int k2 = n1;
    float2 u[16];
#pragma unroll
    for (int j = 0; j < 16; j++) u[j] = row[16*k2 + (j ^ k2)];
    fft16r<SGN>(u);
    __syncwarp();
#pragma unroll
    for (int k1 = 0; k1 < 16; k1++) row[k2 + 16*k1] = u[k1];
    __syncwarp();
}

// ---------------------------------------------------------------------------
// pm kernel
// ---------------------------------------------------------------------------
__global__ __launch_bounds__(256) void kpm(const float* __restrict__ hp,
                                           const float* __restrict__ b1,
                                           const float* __restrict__ W2,
                                           const float* __restrict__ b2,
                                           const float* __restrict__ W3,
                                           const float* __restrict__ b3) {
    __shared__ float smd;
    __shared__ float red[256];
    int tid = threadIdx.x;
    if (tid == 0) {
        float h1[32];
        for (int i = 0; i < 32; i++) h1[i] = fmaxf(b1[i], 0.0f);
        float md = b3[1];
        for (int j = 0; j < 16; j++) {
            float a = b2[j];
            for (int i = 0; i < 32; i++) a += h1[i] * W2[i*16 + j];
            a = fmaxf(a, 0.0f);
            md += a * W3[j*8 + 1];
        }
        smd = md;
    }
    __syncthreads();
    float md = smd;
    float acc = 0.0f;
    for (int t = tid; t < LSIG; t += 256) {
        float tf = (float)t;
        int idx = ((int)(tf * 8.0f / 65537.0f)) & 7;
        float sv = sinf(6.2831853f * tf / 65537.0f);
        float cs = hp[idx*4] + hp[idx*4+1] + hp[idx*4+2] + hp[idx*4+3];
        acc += cs * (1.0f + md * sv);
    }
    red[tid] = acc;
    __syncthreads();
    for (int st = 128; st > 0; st >>= 1) {
        if (tid < st) red[tid] += red[tid + st];
        __syncthreads();
    }
    if (tid == 0) g_pm = red[0] / (65537.0f * 4.0f);
}

// ---------------------------------------------------------------------------
// gain kernel: writes transposed gain table + bin-65536 scalar
// ---------------------------------------------------------------------------
__global__ __launch_bounds__(256) void kgain(const float* __restrict__ bw,
                                             const float* __restrict__ fw) {
    int i = blockIdx.x * 256 + threadIdx.x;
    if (i > 65536) return;
    float f  = (float)((double)i * (22050.0 / 131072.0));
    float ti = (float)i;
    float g = 1.0f;
    const float lo[6] = {1.0f, 4.0f, 8.0f, 13.0f, 30.0f, 100.0f};
    const float hi[6] = {4.0f, 8.0f, 13.0f, 30.0f, 100.0f, 200.0f};
#pragma unroll
    for (int b = 0; b < 6; b++) {
        if (f >= lo[b] && f <= hi[b]) {
            float c  = 0.5f * (lo[b] + hi[b]);
            float sg = (hi[b] - lo[b]) * 0.25f;
            float z  = (f - c) / sg;
            float m  = expf(-0.5f * z * z);
            float tm = sinf(6.2831853f * c * ti / 22050.0f);
            g *= 1.0f + m * bw[b] * (1.0f + 0.2f * tm);
        }
    }
    float pm = g_pm;
    const float sf[8] = {7.83f, 528.0f, 396.0f, 2.5f, 14.1f, 432.0f, 6.0f, 30.0f};
#pragma unroll
    for (int j = 0; j < 8; j++) {
#pragma unroll
        for (int m = 1; m <= 5; m++) {
            double hf = (double)sf[j] * (double)m;
            int hidx = (int)floor(hf * (131072.0 / 22050.0) + 0.5);
            int d = i - hidx;
            if (d >= -15 && d <= 15) {
                float win = expf(-0.5f * (float)(d*d) / 25.0f);
                float enh = fw[j] * win * powf((float)m, -1.2f) * (1.0f + pm);
                g *= 1.0f + enh;
            }
        }
    }
    if (i == 65536) g_g65536 = g;
    else g_gainT[(i & 255) * 256 + (i >> 8)] = g;
}

// ---------------------------------------------------------------------------
// Forward pass 1: 16 rows a per CTA: FFT over b of z[a+256b], * W^{ad},
// write transposed to buf1[d*256+a]. Twiddle via recurrence (2 sincospif).
// ---------------------------------------------------------------------------
__global__ __launch_bounds__(256) void kf1(const float* __restrict__ x) {
    __shared__ float2 sA[16 * RS];
    int tid = threadIdx.x;
    int s   = blockIdx.y;
    int A0  = blockIdx.x * 16;
    const float* xs = x + (size_t)s * LSIG;
    for (int idx = tid; idx < 4096; idx += 256) {
        int al = idx & 15, b = idx >> 4;
        int n  = A0 + al + (b << 8);
        int i2 = 2 * n;
        float re = (i2 <= 65536) ? xs[i2] : 0.0f;
        float im = (i2 <  65536) ? xs[i2 + 1] : 0.0f;
        sA[al * RS + b] = make_float2(re, im);
    }
    __syncthreads();
    {
        int w = tid >> 5, lane = tid & 31;
        fft256p<-1>(sA + (2*w + (lane >> 4)) * RS, lane & 15);
    }
    __syncthreads();
    float2* out = g_buf1 + (size_t)s * N2;
    {
        int al = tid & 15;
        int d0 = tid >> 4;            // 0..15
        int a  = A0 + al;
        float sv, cv;
        sincospif(-(float)(a * d0) / 32768.0f, &sv, &cv);
        float2 wv = make_float2(cv, sv);              // e^{-2pi i a d0/65536}
        sincospif(-(float)a / 2048.0f, &sv, &cv);
        float2 wstep = make_float2(cv, sv);           // e^{-2pi i a*16/65536}
#pragma unroll
        for (int it = 0; it < 16; it++) {
            int d = d0 + 16 * it;
            float2 v = sA[al * RS + d];
            out[d * 256 + a] = cmulf(v, wv);
            wv = cmulf(wv, wstep);
        }
    }
}

// ---------------------------------------------------------------------------
// FUSED middle kernel: kf2 (FFT over a) + spectral + ki1 (IFFT over c).
// Grid (16, NSIG), 512 threads. Block Bx: central rows c0..c0+7 (c0=8Bx+1),
// halos c0-1, c0+8, and all their mirror rows (20 slots). Pair ownership.
// ---------------------------------------------------------------------------
__global__ __launch_bounds__(512, 2) void kmid() {
    extern __shared__ float2 smp[];
    float2* ZS = smp;                 // 20*RSZ  (Z -> gained X -> Zi)
    float2* T  = ZS + 20*RSZ;         // 256: e^{-i pi c/256}
    float2* WR = T + 256;             // 20:  e^{-i pi rowof(sl)/65536}
    float*  MS = (float*)(WR + 20);   // 20*260 magnitudes
    float*  SC = MS + 20*260;         // [2] = |X[65536]|

    const int tid = threadIdx.x;
    const int sig = blockIdx.y;
    const int Bx  = blockIdx.x;
    const int c0  = 8*Bx + 1;
    const float inv = 1.0f / 65536.0f;

    auto rowof = [&](int sl) -> int {
        return (sl < 10) ? ((c0 - 1 + sl) & 255) : ((257 - c0 - (sl - 10)) & 255);
    };

    const float2* in = g_buf1 + (size_t)sig * N2;

    // tables
    if (tid < 256) {
        float sv, cv;
        sincospif(-(float)tid / 256.0f, &sv, &cv);
        T[tid] = make_float2(cv, sv);
    } else if (tid < 276) {
        int sl = tid - 256;
        float sv, cv;
        sincospif(-(float)rowof(sl) / 65536.0f, &sv, &cv);
        WR[sl] = make_float2(cv, sv);
    }
    // load 20 rows (128-bit global loads, split smem stores)
    for (int idx = tid; idx < 20*128; idx += 512) {
        int sl = idx >> 7, cc = idx & 127;
        float4 t = *reinterpret_cast<const float4*>(in + rowof(sl)*256 + 2*cc);
        ZS[sl*RSZ + 2*cc]     = make_float2(t.x, t.y);
        ZS[sl*RSZ + 2*cc + 1] = make_float2(t.z, t.w);
    }
    __syncthreads();

    // phase 1: forward FFT over cols for 20 rows
    {
        int w = tid >> 5, lane = tid & 31;
        if (w < 10) fft256p<-1>(ZS + (2*w + (lane >> 4))*RSZ, lane & 15);
    }
    __syncthreads();

    // phase 2: pair-owned gained X + magnitudes, in place.
#pragma unroll
    for (int t = tid; t < 2560; t += 512) {
        int st = t >> 8, c = t & 255;
        int r  = rowof(st);
        int ps = st + 10;
        int cm = (r == 0) ? ((256 - c) & 255) : (255 - c);
        if (r == 0 && c == 0) {
            float2 z0 = ZS[0];
            float X0 = (z0.x + z0.y) * g_gainT[0];
            float XN = (z0.x - z0.y) * g_g65536;
            ZS[st*RSZ]    = make_float2(X0, 0.f);
            ZS[ps*RSZ]    = make_float2(XN, 0.f);
            MS[st*260]    = fabsf(X0);
            MS[ps*260]    = fabsf(XN);
            SC[2] = fabsf(XN);
            continue;
        }
        float2 zj = ZS[st*RSZ + c];
        float2 zm = ZS[ps*RSZ + cm];
        float Er = 0.5f*(zj.x + zm.x), Ei = 0.5f*(zj.y - zm.y);
        float Or = 0.5f*(zj.y + zm.y), Oi = -0.5f*(zj.x - zm.x);
        float2 W = cmulf(WR[st], T[c]);
        float wor = W.x*Or - W.y*Oi, woi = W.x*Oi + W.y*Or;
        int rm = (256 - r) & 255;
        float gp = g_gainT[(r  << 8) + c];
        float gm = g_gainT[(rm << 8) + cm];
        float XPr = gp*(Er + wor), XPi = gp*(Ei + woi);
        float XMr = gm*(Er - wor), XMi = -gm*(Ei - woi);   // conj applied
        ZS[st*RSZ + c]  = make_float2(XPr, XPi);
        ZS[ps*RSZ + cm] = make_float2(XMr, XMi);
        MS[st*260 + c]  = sqrtf(XPr*XPr + XPi*XPi);
        MS[ps*260 + cm] = sqrtf(XMr*XMr + XMi*XMi);
    }
    __syncthreads();

    // phase 3: smooth-rescale + c2r combine, write both Zi in place.
#pragma unroll
    for (int t = tid; t < 2048; t += 512) {
        int st = (t >> 8) + 1;        // 1..8 (central rows)
        int c  = t & 255;
        int ps = st + 10;
        int cm = 255 - c;
        float2 a0 = ZS[st*RSZ + c];
        float2 b0 = ZS[ps*RSZ + cm];
        float magP = MS[st*260 + c];
        float magM = MS[ps*260 + cm];
        float msP = 0.7f*magP + 0.15f*MS[(st-1)*260 + c] + 0.15f*MS[(st+1)*260 + c];
        float nbM;                     // mag at jm+1
        if (Bx == 0 && st == 1)
            nbM = (c == 0) ? SC[2] : MS[(256 - c)];           // row 0, col 256-c
        else
            nbM = MS[(ps-1)*260 + cm];
        float msM = 0.7f*magM + 0.15f*nbM + 0.15f*MS[(ps+1)*260 + cm];
        float2 a, b;
        if (magP > 0.f) { float rr = msP / magP; a = make_float2(a0.x*rr, a0.y*rr); }
        else a = make_float2(msP, 0.f);
        if (magM > 0.f) { float rr = msM / magM; b = make_float2(b0.x*rr, b0.y*rr); }
        else b = make_float2(msM, 0.f);
        float2 W = cmulf(WR[st], T[c]);
        float er = 0.5f*(a.x + b.x);
        float ei = 0.5f*(a.y - b.y);
        float dr = 0.5f*(a.x - b.x);
        float di = 0.5f*(a.y + b.y);
        float orr = W.x*dr + W.y*di;
        float oi  = W.x*di - W.y*dr;
        ZS[st*RSZ + c]  = make_float2((er - oi)*inv, (ei + orr)*inv);
        ZS[ps*RSZ + cm] = make_float2((er + oi)*inv, (orr - ei)*inv);
    }
    if (Bx == 0 && tid < 256) {
        int c = tid;
        if (c == 0) {
            float X0 = ZS[0].x;
            float XN = ZS[10*RSZ].x;
            ZS[0] = make_float2(0.5f*(X0 + XN)*inv, 0.5f*(X0 - XN)*inv);
        } else {
            float2 a0 = ZS[c];                       // row 0, bin 256c
            float2 b0 = ZS[10*RSZ + (256 - c)];      // bin 65536-256c
            float magP = MS[c];
            float magM = MS[10*260 + (256 - c)];
            float msP = 0.7f*magP + 0.15f*MS[11*260 + (c-1)] + 0.15f*MS[260 + c];
            float msM = 0.7f*magM + 0.15f*MS[11*260 + (255 - c)] + 0.15f*MS[260 + (256 - c)];
            float2 a, b;
            if (magP > 0.f) { float rr = msP / magP; a = make_float2(a0.x*rr, a0.y*rr); }
            else a = make_float2(msP, 0.f);
            if (magM > 0.f) { float rr = msM / magM; b = make_float2(b0.x*rr, b0.y*rr); }
            else b = make_float2(msM, 0.f);
            float2 W = T[c];
            float er = 0.5f*(a.x + b.x);
            float ei = 0.5f*(a.y - b.y);
            float dr = 0.5f*(a.x - b.x);
            float di = 0.5f*(a.y + b.y);
            float orr = W.x*dr + W.y*di;
            float oi  = W.x*di - W.y*dr;
            ZS[c] = make_float2((er - oi)*inv, (ei + orr)*inv);
        }
    }
    __syncthreads();

    // phase 4: inverse FFT over c for output rows (slots 1..8, 11..18, +0)
    {
        int w = tid >> 5, lane = tid & 31;
        if (w < 8) {
            int hw = 2*w + (lane >> 4);                  // 0..15
            int sl = (hw < 8) ? (1 + hw) : (3 + hw);     // 1..8, 11..18
            fft256p<1>(ZS + sl*RSZ, lane & 15);
        } else if (w == 8 && Bx == 0) {
            fft256p<1>(ZS, lane & 15);                   // slot 0 (dup half-warps)
        }
    }
    __syncthreads();

    // phase 5: twiddle * e^{+2pi i d a/65536}, write buf2[a*256+d]
    float2* out = g_buf2 + (size_t)sig * N2;
    {
        int g  = tid >> 8;
        int rl = tid & 7;
        int a0 = (tid & 255) >> 3;     // 0..31
        int sl, d;
        if (g == 0) { sl = 1 + rl;  d = c0 + rl; }
        else        { sl = 18 - rl; d = 249 - c0 + rl; }
        float sv, cv;
        sincospif((float)(d * a0) / 32768.0f, &sv, &cv);
        float2 wv = make_float2(cv, sv);
        sincospif((float)d / 1024.0f, &sv, &cv);
        float2 wstep = make_float2(cv, sv);
#pragma unroll
        for (int it = 0; it < 8; it++) {
            int a = a0 + 32*it;
            float2 v = ZS[sl*RSZ + a];
            out[a * 256 + d] = cmulf(v, wv);
            wv = cmulf(wv, wstep);
        }
    }
    if (Bx == 0 && tid < 256) {
        out[tid * 256 + 0] = ZS[tid];   // row 0, twiddle = 1
    }
}

// ---------------------------------------------------------------------------
// Inverse pass 2: 16 rows a per CTA: IFFT over d -> z[a+256b]; write y.
// ---------------------------------------------------------------------------
__global__ __launch_bounds__(256) void ki2(float* __restrict__ y) {
    __shared__ float2 sA[16 * RS];
    int tid = threadIdx.x;
    int s   = blockIdx.y;
    int A0  = blockIdx.x * 16;
    const float2* in = g_buf2 + (size_t)s * N2;
    for (int idx = tid; idx < 2048; idx += 256) {
        int row = idx >> 7, cc = idx & 127;
        float4 t = *reinterpret_cast<const float4*>(in + (A0 + row)*256 + 2*cc);
        sA[row*RS + 2*cc]     = make_float2(t.x, t.y);
        sA[row*RS + 2*cc + 1] = make_float2(t.z, t.w);
    }
    __syncthreads();
    {
        int w = tid >> 5, lane = tid & 31;
        fft256p<1>(sA + (2*w + (lane >> 4)) * RS, lane & 15);
    }
    __syncthreads();
    float* ys = y + (size_t)s * LSIG;
    for (int idx = tid; idx < 4096; idx += 256) {
        int al = idx & 15, b = idx >> 4;
        int n  = A0 + al + (b << 8);
        int i2 = 2 * n;
        float2 v = sA[al * RS + b];
        if (i2 <= 65536) ys[i2] = v.x;
        if (i2 <  65536) ys[i2 + 1] = v.y;
    }
}

// ---------------------------------------------------------------------------
extern "C" void kernel_launch(void* const* d_in, const int* in_sizes, int n_in,
                              void* d_out, int out_size) {
    const float* x  = (const float*)d_in[0];
    const float* bw = (const float*)d_in[1];
    const float* fw = (const float*)d_in[2];
    const float* hp = (const float*)d_in[3];
    const float* b1 = (const float*)d_in[5];
    const float* W2 = (const float*)d_in[6];
    const float* b2 = (const float*)d_in[7];
    const float* W3 = (const float*)d_in[8];
    const float* b3 = (const float*)d_in[9];
    float* y = (float*)d_out;

    const int KMID_SMEM = (20*RSZ + 256 + 20) * (int)sizeof(float2)
                        + (20*260 + 4) * (int)sizeof(float);
    cudaFuncSetAttribute(kmid, cudaFuncAttributeMaxDynamicSharedMemorySize, KMID_SMEM);

    kpm<<<1, 256>>>(hp, b1, W2, b2, W3, b3);
    kgain<<<257, 256>>>(bw, fw);
    kf1<<<dim3(16, NSIG), 256>>>(x);
    kmid<<<dim3(16, NSIG), 512, KMID_SMEM>>>();
    ki2<<<dim3(16, NSIG), 256>>>(y);
}

// round 12
// speedup vs baseline: 1.5008x; 1.1767x over previous
#include <cuda_runtime.h>
#include <math.h>

// Problem constants
#define NSIG 256          // B*C = 128*2 signals
#define LSIG 65537        // signal length (== RLEN)
#define N2   65536        // packed complex FFT length (NFFT/2)
#define RS   257          // smem row stride in float2 (kf1/ki2)
#define RSZ  257          // smem row stride in float2 (kmid)
#define MSS  257          // magnitude row stride (floats)
#define NC   16           // central rows per kmid block
#define NSL  18           // forward slots (NC + 2 halos)

// Scratch (allowed: __device__ globals, no allocation)
__device__ __align__(16) float2 g_buf1[(size_t)NSIG * N2];   // 134 MB
__device__ __align__(16) float2 g_buf2[(size_t)NSIG * N2];   // 134 MB
__device__ float  g_gainT[65536];              // gain transposed: [r*256+c] = gain[r+256c]
__device__ float  g_g65536;                    // gain at bin 65536
__device__ float  g_pm;
__device__ float  g_md;
__device__ float  g_part[64];

__device__ __forceinline__ float2 cmulf(float2 a, float2 b) {
    return make_float2(a.x*b.x - a.y*b.y, a.x*b.y + a.y*b.x);
}

// ---------------------------------------------------------------------------
// Register-resident 16-point FFT (Stockham radix-2, natural order in/out).
// ---------------------------------------------------------------------------
template<int SGN, int M>
__device__ __forceinline__ void fstage16(const float2* A, float2* B) {
    const float CU[8] = {1.f, 0.92387953251f, 0.70710678119f, 0.38268343236f,
                         0.f, -0.38268343236f, -0.70710678119f, -0.92387953251f};
    const float SU[8] = {0.f, 0.38268343236f, 0.70710678119f, 0.92387953251f,
                         1.f, 0.92387953251f, 0.70710678119f, 0.38268343236f};
#pragma unroll
    for (int t = 0; t < 8; t++) {
        int u = t & ~(M - 1);
        int o = t + u;
        float2 c0 = A[t], c1 = A[t + 8];
        float wr = CU[u], wi = (float)SGN * SU[u];
        B[o] = make_float2(c0.x + c1.x, c0.y + c1.y);
        float dr = c0.x - c1.x, di = c0.y - c1.y;
        B[o + M] = make_float2(wr*dr - wi*di, wr*di + wi*dr);
    }
}

template<int SGN>
__device__ __forceinline__ void fft16r(float2* v) {
    float2 b[16];
    fstage16<SGN, 1>(v, b);
    fstage16<SGN, 2>(b, v);
    fstage16<SGN, 4>(v, b);
    fstage16<SGN, 8>(b, v);   // result back in v
}

// ---------------------------------------------------------------------------
// 256-point FFT of one row (half-warp per row). 16x16 decomposition,
// 2 smem round trips, XOR-swizzled intermediate, recurrence twiddles.
// ---------------------------------------------------------------------------
template<int SGN>
__device__ __forceinline__ void fft256p(float2* row, int n1) {
    float2 v[16];
#pragma unroll
    for (int j = 0; j < 16; j++) v[j] = row[n1 + 16*j];
    fft16r<SGN>(v);
    float si, co;
    sincospif((float)SGN * (float)n1 * (1.0f/128.0f), &si, &co);
    float2 w1 = make_float2(co, si);
    float2 wv = w1;
#pragma unroll
    for (int k2 = 1; k2 < 16; k2++) { v[k2] = cmulf(v[k2], wv); wv = cmulf(wv, w1); }
    __syncwarp();
#pragma unroll
    for (int k2 = 0; k2 < 16; k2++) row[16*k2 + (n1 ^ k2)] = v[k2];
    __syncwarp();
    int k2 = n1;
    float2 u[16];
#pragma unroll
    for (int j = 0; j < 16; j++) u[j] = row[16*k2 + (j ^ k2)];
    fft16r<SGN>(u);
    __syncwarp();
#pragma unroll
    for (int k1 = 0; k1 < 16; k1++) row[k2 + 16*k1] = u[k1];
    __syncwarp();
}

// ---------------------------------------------------------------------------
// pm kernels: (0) tiny MLP -> g_md, (r) 64-block partial sums, (2) reduce.
// ---------------------------------------------------------------------------
__global__ void kpm0(const float* __restrict__ b1, const float* __restrict__ W2,
                     const float* __restrict__ b2, const float* __restrict__ W3,
                     const float* __restrict__ b3) {
    __shared__ float aj[16];
    int tid = threadIdx.x;
    if (tid < 16) {
        float a = b2[tid];
        for (int i = 0; i < 32; i++) a += fmaxf(b1[i], 0.0f) * W2[i*16 + tid];
        aj[tid] = fmaxf(a, 0.0f);
    }
    __syncwarp();
    if (tid == 0) {
        float md = b3[1];
        for (int j = 0; j < 16; j++) md += aj[j] * W3[j*8 + 1];
        g_md = md;
    }
}

__global__ __launch_bounds__(256) void kpmr(const float* __restrict__ hp) {
    __shared__ float red[256];
    int tid = threadIdx.x;
    float md = g_md;
    float acc = 0.0f;
    for (int t = blockIdx.x * 256 + tid; t < LSIG; t += 64*256) {
        float tf = (float)t;
        int idx = ((int)(tf * 8.0f / 65537.0f)) & 7;
        float sv = sinf(6.2831853f * tf / 65537.0f);
        float cs = hp[idx*4] + hp[idx*4+1] + hp[idx*4+2] + hp[idx*4+3];
        acc += cs * (1.0f + md * sv);
    }
    red[tid] = acc;
    __syncthreads();
    for (int st = 128; st > 0; st >>= 1) {
        if (tid < st) red[tid] += red[tid + st];
        __syncthreads();
    }
    if (tid == 0) g_part[blockIdx.x] = red[0];
}

__global__ void kpm2() {
    if (threadIdx.x == 0) {
        float s = 0.0f;
        for (int i = 0; i < 64; i++) s += g_part[i];   // fixed order: deterministic
        g_pm = s / (65537.0f * 4.0f);
    }
}

// ---------------------------------------------------------------------------
// gain kernel: writes transposed gain table + bin-65536 scalar
// ---------------------------------------------------------------------------
__global__ __launch_bounds__(256) void kgain(const float* __restrict__ bw,
                                             const float* __restrict__ fw) {
    int i = blockIdx.x * 256 + threadIdx.x;
    if (i > 65536) return;
    float f  = (float)((double)i * (22050.0 / 131072.0));
    float ti = (float)i;
    float g = 1.0f;
    const float lo[6] = {1.0f, 4.0f, 8.0f, 13.0f, 30.0f, 100.0f};
    const float hi[6] = {4.0f, 8.0f, 13.0f, 30.0f, 100.0f, 200.0f};
#pragma unroll
    for (int b = 0; b < 6; b++) {
        if (f >= lo[b] && f <= hi[b]) {
            float c  = 0.5f * (lo[b] + hi[b]);
            float sg = (hi[b] - lo[b]) * 0.25f;
            float z  = (f - c) / sg;
            float m  = expf(-0.5f * z * z);
            float tm = sinf(6.2831853f * c * ti / 22050.0f);
            g *= 1.0f + m * bw[b] * (1.0f + 0.2f * tm);
        }
    }
    float pm = g_pm;
    const float sf[8] = {7.83f, 528.0f, 396.0f, 2.5f, 14.1f, 432.0f, 6.0f, 30.0f};
#pragma unroll
    for (int j = 0; j < 8; j++) {
#pragma unroll
        for (int m = 1; m <= 5; m++) {
            double hf = (double)sf[j] * (double)m;
            int hidx = (int)floor(hf * (131072.0 / 22050.0) + 0.5);
            int d = i - hidx;
            if (d >= -15 && d <= 15) {
                float win = expf(-0.5f * (float)(d*d) / 25.0f);
                float enh = fw[j] * win * powf((float)m, -1.2f) * (1.0f + pm);
                g *= 1.0f + enh;
            }
        }
    }
    if (i == 65536) g_g65536 = g;
    else g_gainT[(i & 255) * 256 + (i >> 8)] = g;
}

// ---------------------------------------------------------------------------
// Forward pass 1: 16 rows a per CTA: FFT over b of z[a+256b], * W^{ad},
// write transposed to buf1[d*256+a]. Twiddle via recurrence (2 sincospif).
// ---------------------------------------------------------------------------
__global__ __launch_bounds__(256) void kf1(const float* __restrict__ x) {
    __shared__ float2 sA[16 * RS];
    int tid = threadIdx.x;
    int s   = blockIdx.y;
    int A0  = blockIdx.x * 16;
    const float* xs = x + (size_t)s * LSIG;
    for (int idx = tid; idx < 4096; idx += 256) {
        int al = idx & 15, b = idx >> 4;
        int n  = A0 + al + (b << 8);
        int i2 = 2 * n;
        float re = (i2 <= 65536) ? xs[i2] : 0.0f;
        float im = (i2 <  65536) ? xs[i2 + 1] : 0.0f;
        sA[al * RS + b] = make_float2(re, im);
    }
    __syncthreads();
    {
        int w = tid >> 5, lane = tid & 31;
        fft256p<-1>(sA + (2*w + (lane >> 4)) * RS, lane & 15);
    }
    __syncthreads();
    float2* out = g_buf1 + (size_t)s * N2;
    {
        int al = tid & 15;
        int d0 = tid >> 4;            // 0..15
        int a  = A0 + al;
        float sv, cv;
        sincospif(-(float)(a * d0) / 32768.0f, &sv, &cv);
        float2 wv = make_float2(cv, sv);              // e^{-2pi i a d0/65536}
        sincospif(-(float)a / 2048.0f, &sv, &cv);
        float2 wstep = make_float2(cv, sv);           // e^{-2pi i a*16/65536}
#pragma unroll
        for (int it = 0; it < 16; it++) {
            int d = d0 + 16 * it;
            float2 v = sA[al * RS + d];
            out[d * 256 + a] = cmulf(v, wv);
            wv = cmulf(wv, wstep);
        }
    }
}

// ---------------------------------------------------------------------------
// FUSED middle kernel: FFT over a + spectral + IFFT over c.
// Grid (8, NSIG), 512 threads. Block Bx: central rows c0..c0+15 (c0=16Bx+1),
// halos c0-1, c0+16, and all mirror rows: 36 slots (fw 0..17, mir 18..35).
// Pair ownership; recurrence twiddles; coalesced phase-5 stores.
// ---------------------------------------------------------------------------
__global__ __launch_bounds__(512, 2) void kmid() {
    extern __shared__ float2 smp[];
    float2* ZS = smp;                 // 36*RSZ  (Z -> gained X -> Zi)
    float2* T  = ZS + 36*RSZ;         // 256: e^{-i pi c/256}
    float2* WR = T + 256;             // 36:  e^{-i pi rowof(sl)/65536}
    float*  MS = (float*)(WR + 36);   // 36*MSS magnitudes
    float*  SC = MS + 36*MSS;         // [2] = |X[65536]|

    const int tid = threadIdx.x;
    const int sig = blockIdx.y;
    const int Bx  = blockIdx.x;
    const int c0  = NC*Bx + 1;
    const float inv = 1.0f / 65536.0f;

    auto rowof = [&](int sl) -> int {
        return (sl < NSL) ? ((c0 - 1 + sl) & 255) : ((257 - c0 - (sl - NSL)) & 255);
    };

    const float2* in = g_buf1 + (size_t)sig * N2;

    // tables
    if (tid < 256) {
        float sv, cv;
        sincospif(-(float)tid / 256.0f, &sv, &cv);
        T[tid] = make_float2(cv, sv);
    } else if (tid < 256 + 36) {
        int sl = tid - 256;
        float sv, cv;
        sincospif(-(float)rowof(sl) / 65536.0f, &sv, &cv);
        WR[sl] = make_float2(cv, sv);
    }
    // load 36 rows (128-bit global loads)
    for (int idx = tid; idx < 36*128; idx += 512) {
        int sl = idx >> 7, cc = idx & 127;
        float4 t = *reinterpret_cast<const float4*>(in + rowof(sl)*256 + 2*cc);
        ZS[sl*RSZ + 2*cc]     = make_float2(t.x, t.y);
        ZS[sl*RSZ + 2*cc + 1] = make_float2(t.z, t.w);
    }
    __syncthreads();

    // phase 1: forward FFT over cols for 36 rows (32 + 4)
    {
        int w = tid >> 5, lane = tid & 31, n1 = lane & 15;
        int hw = 2*w + (lane >> 4);                  // 0..31
        fft256p<-1>(ZS + hw*RSZ, n1);
        if (hw < 4) fft256p<-1>(ZS + (32 + hw)*RSZ, n1);
    }
    __syncthreads();

    // phase 2: pair-owned gained X + magnitudes, in place.
#pragma unroll
    for (int t = tid; t < NSL*256; t += 512) {
        int sl = t >> 8, c = t & 255;
        int r  = rowof(sl);
        int ps = sl + NSL;
        int cm = (r == 0) ? ((256 - c) & 255) : (255 - c);
        if (r == 0 && c == 0) {
            float2 z0 = ZS[0];
            float X0 = (z0.x + z0.y) * g_gainT[0];
            float XN = (z0.x - z0.y) * g_g65536;
            ZS[sl*RSZ]    = make_float2(X0, 0.f);
            ZS[ps*RSZ]    = make_float2(XN, 0.f);
            MS[sl*MSS]    = fabsf(X0);
            MS[ps*MSS]    = fabsf(XN);
            SC[2] = fabsf(XN);
            continue;
        }
        float2 zj = ZS[sl*RSZ + c];
        float2 zm = ZS[ps*RSZ + cm];
        float Er = 0.5f*(zj.x + zm.x), Ei = 0.5f*(zj.y - zm.y);
        float Or = 0.5f*(zj.y + zm.y), Oi = -0.5f*(zj.x - zm.x);
        float2 W = cmulf(WR[sl], T[c]);
        float wor = W.x*Or - W.y*Oi, woi = W.x*Oi + W.y*Or;
        int rm = (256 - r) & 255;
        float gp = g_gainT[(r  << 8) + c];
        float gm = g_gainT[(rm << 8) + cm];
        float XPr = gp*(Er + wor), XPi = gp*(Ei + woi);
        float XMr = gm*(Er - wor), XMi = -gm*(Ei - woi);   // conj applied
        ZS[sl*RSZ + c]  = make_float2(XPr, XPi);
        ZS[ps*RSZ + cm] = make_float2(XMr, XMi);
        MS[sl*MSS + c]  = sqrtf(XPr*XPr + XPi*XPi);
        MS[ps*MSS + cm] = sqrtf(XMr*XMr + XMi*XMi);
    }
    __syncthreads();

    // phase 3: smooth-rescale + c2r combine, write both Zi in place.
#pragma unroll
    for (int t = tid; t < NC*256; t += 512) {
        int st = (t >> 8) + 1;        // 1..16 (central rows)
        int c  = t & 255;
        int ps = st + NSL;
        int cm = 255 - c;
        float2 a0 = ZS[st*RSZ + c];
        float2 b0 = ZS[ps*RSZ + cm];
        float magP = MS[st*MSS + c];
        float magM = MS[ps*MSS + cm];
        float msP = 0.7f*magP + 0.15f*MS[(st-1)*MSS + c] + 0.15f*MS[(st+1)*MSS + c];
        float nbM;                     // mag at jm+1
        if (Bx == 0 && st == 1)
            nbM = (c == 0) ? SC[2] : MS[(256 - c)];           // row 0, col 256-c
        else
            nbM = MS[(ps-1)*MSS + cm];
        float msM = 0.7f*magM + 0.15f*nbM + 0.15f*MS[(ps+1)*MSS + cm];
        float2 a, b;
        if (magP > 0.f) { float rr = msP / magP; a = make_float2(a0.x*rr, a0.y*rr); }
        else a = make_float2(msP, 0.f);
        if (magM > 0.f) { float rr = msM / magM; b = make_float2(b0.x*rr, b0.y*rr); }
        else b = make_float2(msM, 0.f);
        float2 W = cmulf(WR[st], T[c]);
        float er = 0.5f*(a.x + b.x);
        float ei = 0.5f*(a.y - b.y);
        float dr = 0.5f*(a.x - b.x);
        float di = 0.5f*(a.y + b.y);
        float orr = W.x*dr + W.y*di;
        float oi  = W.x*di - W.y*dr;
        ZS[st*RSZ + c]  = make_float2((er - oi)*inv, (ei + orr)*inv);
        ZS[ps*RSZ + cm] = make_float2((er + oi)*inv, (orr - ei)*inv);
    }
    if (Bx == 0 && tid < 256) {
        int c = tid;
        if (c == 0) {
            float X0 = ZS[0].x;
            float XN = ZS[NSL*RSZ].x;
            ZS[0] = make_float2(0.5f*(X0 + XN)*inv, 0.5f*(X0 - XN)*inv);
        } else {
            float2 a0 = ZS[c];                            // row 0, bin 256c
            float2 b0 = ZS[NSL*RSZ + (256 - c)];          // bin 65536-256c
            float magP = MS[c];
            float magM = MS[NSL*MSS + (256 - c)];
            float msP = 0.7f*magP + 0.15f*MS[(NSL+1)*MSS + (c-1)] + 0.15f*MS[MSS + c];
            float msM = 0.7f*magM + 0.15f*MS[(NSL+1)*MSS + (255 - c)] + 0.15f*MS[MSS + (256 - c)];
            float2 a, b;
            if (magP > 0.f) { float rr = msP / magP; a = make_float2(a0.x*rr, a0.y*rr); }
            else a = make_float2(msP, 0.f);
            if (magM > 0.f) { float rr = msM / magM; b = make_float2(b0.x*rr, b0.y*rr); }
            else b = make_float2(msM, 0.f);
            float2 W = T[c];
            float er = 0.5f*(a.x + b.x);
            float ei = 0.5f*(a.y - b.y);
            float dr = 0.5f*(a.x - b.x);
            float di = 0.5f*(a.y + b.y);
            float orr = W.x*dr + W.y*di;
            float oi  = W.x*di - W.y*dr;
            ZS[c] = make_float2((er - oi)*inv, (ei + orr)*inv);
        }
    }
    __syncthreads();

    // phase 4: inverse FFT over c (slots 1..16, 19..34 -> 32 half-warps full)
    {
        int w = tid >> 5, lane = tid & 31, n1 = lane & 15;
        int hw = 2*w + (lane >> 4);                  // 0..31
        int sl = (hw < 16) ? (hw + 1) : (hw + 3);    // 1..16, 19..34
        fft256p<1>(ZS + sl*RSZ, n1);
        if (Bx == 0 && w == 0) fft256p<1>(ZS, n1);   // slot 0 (dup halves, benign)
    }
    __syncthreads();

    // phase 5: twiddle * e^{+2pi i d a/65536}, write buf2[a*256+d] (coalesced in d)
    float2* out = g_buf2 + (size_t)sig * N2;
    {
        int g  = tid >> 8;             // 0: fw rows, 1: mirror rows
        int u  = tid & 255;
        int rl = u & 15;               // d offset (consecutive across lanes)
        int a0 = u >> 4;               // 0..15
        int sl, d;
        if (g == 0) { sl = 1 + rl;        d = c0 + rl; }
        else        { sl = NSL + 1 + rl;  d = (256 - c0 - rl) & 255; }
        float sv, cv;
        sincospif((float)(d * a0) / 32768.0f, &sv, &cv);
        float2 wv = make_float2(cv, sv);
        sincospif((float)d / 2048.0f, &sv, &cv);
        float2 wstep = make_float2(cv, sv);           // e^{+2pi i 16 d/65536}
#pragma unroll
        for (int it = 0; it < 16; it++) {
            int a = a0 + 16*it;
            float2 v = ZS[sl*RSZ + a];
            out[a * 256 + d] = cmulf(v, wv);
            wv = cmulf(wv, wstep);
        }
    }
    if (Bx == 0 && tid < 256) {
        out[tid * 256 + 0] = ZS[tid];   // row 0, twiddle = 1
    }
}

// ---------------------------------------------------------------------------
// Inverse pass 2: 16 rows a per CTA: IFFT over d -> z[a+256b]; write y.
// ---------------------------------------------------------------------------
__global__ __launch_bounds__(256) void ki2(float* __restrict__ y) {
    __shared__ float2 sA[16 * RS];
    int tid = threadIdx.x;
    int s   = blockIdx.y;
    int A0  = blockIdx.x * 16;
    const float2* in = g_buf2 + (size_t)s * N2;
    for (int idx = tid; idx < 2048; idx += 256) {
        int row = idx >> 7, cc = idx & 127;
        float4 t = *reinterpret_cast<const float4*>(in + (A0 + row)*256 + 2*cc);
        sA[row*RS + 2*cc]     = make_float2(t.x, t.y);
        sA[row*RS + 2*cc + 1] = make_float2(t.z, t.w);
    }
    __syncthreads();
    {
        int w = tid >> 5, lane = tid & 31;
        fft256p<1>(sA + (2*w + (lane >> 4)) * RS, lane & 15);
    }
    __syncthreads();
    float* ys = y + (size_t)s * LSIG;
    for (int idx = tid; idx < 4096; idx += 256) {
        int al = idx & 15, b = idx >> 4;
        int n  = A0 + al + (b << 8);
        int i2 = 2 * n;
        float2 v = sA[al * RS + b];
        if (i2 <= 65536) ys[i2] = v.x;
        if (i2 <  65536) ys[i2 + 1] = v.y;
    }
}

// ---------------------------------------------------------------------------
extern "C" void kernel_launch(void* const* d_in, const int* in_sizes, int n_in,
                              void* d_out, int out_size) {
    const float* x  = (const float*)d_in[0];
    const float* bw = (const float*)d_in[1];
    const float* fw = (const float*)d_in[2];
    const float* hp = (const float*)d_in[3];
    const float* b1 = (const float*)d_in[5];
    const float* W2 = (const float*)d_in[6];
    const float* b2 = (const float*)d_in[7];
    const float* W3 = (const float*)d_in[8];
    const float* b3 = (const float*)d_in[9];
    float* y = (float*)d_out;

    const int KMID_SMEM = (36*RSZ + 256 + 36) * (int)sizeof(float2)
                        + (36*MSS + 4) * (int)sizeof(float);
    cudaFuncSetAttribute(kmid, cudaFuncAttributeMaxDynamicSharedMemorySize, KMID_SMEM);

    kpm0<<<1, 32>>>(b1, W2, b2, W3, b3);
    kpmr<<<64, 256>>>(hp);
    kpm2<<<1, 32>>>();
    kgain<<<257, 256>>>(bw, fw);
    kf1<<<dim3(16, NSIG), 256>>>(x);
    kmid<<<dim3(8, NSIG), 512, KMID_SMEM>>>();
    ki2<<<dim3(16, NSIG), 256>>>(y);
}

// round 14
// speedup vs baseline: 1.6037x; 1.0686x over previous
#include <cuda_runtime.h>
#include <math.h>

// Problem constants
#define NSIG 256          // B*C = 128*2 signals
#define LSIG 65537        // signal length (== RLEN)
#define N2   65536        // packed complex FFT length (NFFT/2)
#define RS   257          // smem row stride in float2 (kf1/ki2)
#define RSZ  257          // smem row stride in float2 (kmid)
#define MSS  257          // magnitude row stride (floats)
#define NC   16           // central rows per kmid block
#define NSL  18           // forward slots (NC + 2 halos)

// Scratch (allowed: __device__ globals, no allocation)
__device__ __align__(16) float2 g_buf1[(size_t)NSIG * N2];   // 134 MB
__device__ __align__(16) float2 g_buf2[(size_t)NSIG * N2];   // 134 MB
__device__ float  g_gainT[65536];              // gain transposed: [r*256+c] = gain[r+256c]
__device__ float  g_g65536;                    // gain at bin 65536
__device__ float  g_pm;
__device__ float  g_md;
__device__ float  g_part[64];

__device__ __forceinline__ float2 cmulf(float2 a, float2 b) {
    return make_float2(a.x*b.x - a.y*b.y, a.x*b.y + a.y*b.x);
}

// ---------------------------------------------------------------------------
// Packed f32x2 complex helpers (sm_103a PTX-only 2-wide fp32 ops).
// A complex value (re, im) lives in one 64-bit register pair.
// ---------------------------------------------------------------------------
typedef unsigned long long u64c;
#define NEG1C 0xBF800000BF800000ULL   // packed (-1.0f, -1.0f)

__device__ __forceinline__ u64c pk2(float lo, float hi) {
    u64c r; asm("mov.b64 %0, {%1, %2};" : "=l"(r) : "f"(lo), "f"(hi)); return r;
}
__device__ __forceinline__ float2 u2f(u64c p) {
    float2 v; asm("mov.b64 {%0, %1}, %2;" : "=f"(v.x), "=f"(v.y) : "l"(p)); return v;
}
__device__ __forceinline__ u64c addp(u64c a, u64c b) {
    u64c r; asm("add.rn.f32x2 %0, %1, %2;" : "=l"(r) : "l"(a), "l"(b)); return r;
}
__device__ __forceinline__ u64c mulp(u64c a, u64c b) {
    u64c r; asm("mul.rn.f32x2 %0, %1, %2;" : "=l"(r) : "l"(a), "l"(b)); return r;
}
__device__ __forceinline__ u64c fmap(u64c a, u64c b, u64c c) {
    u64c r; asm("fma.rn.f32x2 %0, %1, %2, %3;" : "=l"(r) : "l"(a), "l"(b), "l"(c)); return r;
}
__device__ __forceinline__ u64c swapp(u64c a) {
    float lo, hi; asm("mov.b64 {%0, %1}, %2;" : "=f"(lo), "=f"(hi) : "l"(a));
    return pk2(hi, lo);
}

// ---------------------------------------------------------------------------
// Packed register-resident 16-point FFT (Stockham radix-2, natural order).
// Butterfly: sum = add.f32x2; diff = fma(c1, -1, c0); twiddle cmul =
// fma(swap(d), (-wi,wi), d*(wr,wr)) with compile-time-hoisted constants.
// ---------------------------------------------------------------------------
template<int SGN, int M>
__device__ __forceinline__ void fstage16p(const u64c* A, u64c* B) {
    const float CU[8] = {1.f, 0.92387953251f, 0.70710678119f, 0.38268343236f,
                         0.f, -0.38268343236f, -0.70710678119f, -0.92387953251f};
    const float SU[8] = {0.f, 0.38268343236f, 0.70710678119f, 0.92387953251f,
                         1.f, 0.92387953251f, 0.70710678119f, 0.38268343236f};
#pragma unroll
    for (int t = 0; t < 8; t++) {
        int u = t & ~(M - 1);
        int o = t + u;
        u64c c0 = A[t], c1 = A[t + 8];
        u64c s = addp(c0, c1);
        u64c d = fmap(c1, (u64c)NEG1C, c0);
        B[o] = s;
        if (u == 0) {
            B[o + M] = d;
        } else {
            float wr = CU[u], wi = (float)SGN * SU[u];
            u64c wrr = pk2(wr, wr);
            u64c wsp = pk2(-wi, wi);
            B[o + M] = fmap(swapp(d), wsp, mulp(d, wrr));
        }
    }
}

template<int SGN>
__device__ __forceinline__ void fft16rp(u64c* v) {
    u64c b[16];
    fstage16p<SGN, 1>(v, b);
    fstage16p<SGN, 2>(b, v);
    fstage16p<SGN, 4>(v, b);
    fstage16p<SGN, 8>(b, v);   // result back in v
}

// ---------------------------------------------------------------------------
// 256-point FFT of one row (half-warp per row). 16x16 decomposition,
// 2 smem round trips, XOR-swizzled intermediate, recurrence twiddles,
// packed-f32x2 radix-16 cores.
// ---------------------------------------------------------------------------
template<int SGN>
__device__ __forceinline__ void fft256p(float2* row, int n1) {
    u64c v[16];
#pragma unroll
    for (int j = 0; j < 16; j++) { float2 t = row[n1 + 16*j]; v[j] = pk2(t.x, t.y); }
    fft16rp<SGN>(v);
    float si, co;
    sincospif((float)SGN * (float)n1 * (1.0f/128.0f), &si, &co);
    float2 w1 = make_float2(co, si);
    float2 wv = w1;
#pragma unroll
    for (int k2 = 1; k2 < 16; k2++) {
        float2 t = u2f(v[k2]);
        v[k2] = pk2(t.x*wv.x - t.y*wv.y, t.x*wv.y + t.y*wv.x);
        wv = cmulf(wv, w1);
    }
    __syncwarp();
#pragma unroll
    for (int k2 = 0; k2 < 16; k2++) row[16*k2 + (n1 ^ k2)] = u2f(v[k2]);
    __syncwarp();
    int k2 = n1;
    u64c u[16];
#pragma unroll
    for (int j = 0; j < 16; j++) { float2 t = row[16*k2 + (j ^ k2)]; u[j] = pk2(t.x, t.y); }
    fft16rp<SGN>(u);
    __syncwarp();
#pragma unroll
    for (int k1 = 0; k1 < 16; k1++) row[k2 + 16*k1] = u2f(u[k1]);
    __syncwarp();
}

// ---------------------------------------------------------------------------
// pm kernels: (0) tiny MLP -> g_md, (r) 64-block partial sums, (2) reduce.
// ---------------------------------------------------------------------------
__global__ void kpm0(const float* __restrict__ b1, const float* __restrict__ W2,
                     const float* __restrict__ b2, const float* __restrict__ W3,
                     const float* __restrict__ b3) {
    __shared__ float aj[16];
    int tid = threadIdx.x;
    if (tid < 16) {
        float a = b2[tid];
        for (int i = 0; i < 32; i++) a += fmaxf(b1[i], 0.0f) * W2[i*16 + tid];
        aj[tid] = fmaxf(a, 0.0f);
    }
    __syncwarp();
    if (tid == 0) {
        float md = b3[1];
        for (int j = 0; j < 16; j++) md += aj[j] * W3[j*8 + 1];
        g_md = md;
    }
}

__global__ __launch_bounds__(256) void kpmr(const float* __restrict__ hp) {
    __shared__ float red[256];
    int tid = threadIdx.x;
    float md = g_md;
    float acc = 0.0f;
    for (int t = blockIdx.x * 256 + tid; t < LSIG; t += 64*256) {
        float tf = (float)t;
        int idx = ((int)(tf * 8.0f / 65537.0f)) & 7;
        float sv = sinf(6.2831853f * tf / 65537.0f);
        float cs = hp[idx*4] + hp[idx*4+1] + hp[idx*4+2] + hp[idx*4+3];
        acc += cs * (1.0f + md * sv);
    }
    red[tid] = acc;
    __syncthreads();
    for (int st = 128; st > 0; st >>= 1) {
        if (tid < st) red[tid] += red[tid + st];
        __syncthreads();
    }
    if (tid == 0) g_part[blockIdx.x] = red[0];
}

__global__ void kpm2() {
    if (threadIdx.x == 0) {
        float s = 0.0f;
        for (int i = 0; i < 64; i++) s += g_part[i];   // fixed order: deterministic
        g_pm = s / (65537.0f * 4.0f);
    }
}

// ---------------------------------------------------------------------------
// gain kernel: writes transposed gain table + bin-65536 scalar
// ---------------------------------------------------------------------------
__global__ __launch_bounds__(256) void kgain(const float* __restrict__ bw,
                                             const float* __restrict__ fw) {
    int i = blockIdx.x * 256 + threadIdx.x;
    if (i > 65536) return;
    float f  = (float)((double)i * (22050.0 / 131072.0));
    float ti = (float)i;
    float g = 1.0f;
    const float lo[6] = {1.0f, 4.0f, 8.0f, 13.0f, 30.0f, 100.0f};
    const float hi[6] = {4.0f, 8.0f, 13.0f, 30.0f, 100.0f, 200.0f};
#pragma unroll
    for (int b = 0; b < 6; b++) {
        if (f >= lo[b] && f <= hi[b]) {
            float c  = 0.5f * (lo[b] + hi[b]);
            float sg = (hi[b] - lo[b]) * 0.25f;
            float z  = (f - c) / sg;
            float m  = expf(-0.5f * z * z);
            float tm = sinf(6.2831853f * c * ti / 22050.0f);
            g *= 1.0f + m * bw[b] * (1.0f + 0.2f * tm);
        }
    }
    float pm = g_pm;
    const float sf[8] = {7.83f, 528.0f, 396.0f, 2.5f, 14.1f, 432.0f, 6.0f, 30.0f};
#pragma unroll
    for (int j = 0; j < 8; j++) {
#pragma unroll
        for (int m = 1; m <= 5; m++) {
            double hf = (double)sf[j] * (double)m;
            int hidx = (int)floor(hf * (131072.0 / 22050.0) + 0.5);
            int d = i - hidx;
            if (d >= -15 && d <= 15) {
                float win = expf(-0.5f * (float)(d*d) / 25.0f);
                float enh = fw[j] * win * powf((float)m, -1.2f) * (1.0f + pm);
                g *= 1.0f + enh;
            }
        }
    }
    if (i == 65536) g_g65536 = g;
    else g_gainT[(i & 255) * 256 + (i >> 8)] = g;
}

// ---------------------------------------------------------------------------
// Forward pass 1: 16 rows a per CTA: FFT over b of z[a+256b], * W^{ad},
// write transposed to buf1[d*256+a]. Twiddle via recurrence (2 sincospif).
// ---------------------------------------------------------------------------
__global__ __launch_bounds__(256) void kf1(const float* __restrict__ x) {
    __shared__ float2 sA[16 * RS];
    int tid = threadIdx.x;
    int s   = blockIdx.y;
    int A0  = blockIdx.x * 16;
    const float* xs = x + (size_t)s * LSIG;
    for (int idx = tid; idx < 4096; idx += 256) {
        int al = idx & 15, b = idx >> 4;
        int n  = A0 + al + (b << 8);
        int i2 = 2 * n;
        float re = (i2 <= 65536) ? xs[i2] : 0.0f;
        float im = (i2 <  65536) ? xs[i2 + 1] : 0.0f;
        sA[al * RS + b] = make_float2(re, im);
    }
    __syncthreads();
    {
        int w = tid >> 5, lane = tid & 31;
        fft256p<-1>(sA + (2*w + (lane >> 4)) * RS, lane & 15);
    }
    __syncthreads();
    float2* out = g_buf1 + (size_t)s * N2;
    {
        int al = tid & 15;
        int d0 = tid >> 4;            // 0..15
        int a  = A0 + al;
        float sv, cv;
        sincospif(-(float)(a * d0) / 32768.0f, &sv, &cv);
        float2 wv = make_float2(cv, sv);              // e^{-2pi i a d0/65536}
        sincospif(-(float)a / 2048.0f, &sv, &cv);
        float2 wstep = make_float2(cv, sv);           // e^{-2pi i a*16/65536}
#pragma unroll
        for (int it = 0; it < 16; it++) {
            int d = d0 + 16 * it;
            float2 v = sA[al * RS + d];
            out[d * 256 + a] = cmulf(v, wv);
            wv = cmulf(wv, wstep);
        }
    }
}

// ---------------------------------------------------------------------------
// FUSED middle kernel: FFT over a + spectral + IFFT over c.
// Grid (8, NSIG), 512 threads. Block Bx: central rows c0..c0+15 (c0=16Bx+1),
// halos c0-1, c0+16, and all mirror rows: 36 slots (fw 0..17, mir 18..35).
// Pair ownership; recurrence twiddles; coalesced phase-5 stores.
// ---------------------------------------------------------------------------
__global__ __launch_bounds__(512, 2) void kmid() {
    extern __shared__ float2 smp[];
    float2* ZS = smp;                 // 36*RSZ  (Z -> gained X -> Zi)
    float2* T  = ZS + 36*RSZ;         // 256: e^{-i pi c/256}
    float2* WR = T + 256;             // 36:  e^{-i pi rowof(sl)/65536}
    float*  MS = (float*)(WR + 36);   // 36*MSS magnitudes
    float*  SC = MS + 36*MSS;         // [2] = |X[65536]|

    const int tid = threadIdx.x;
    const int sig = blockIdx.y;
    const int Bx  = blockIdx.x;
    const int c0  = NC*Bx + 1;
    const float inv = 1.0f / 65536.0f;

    auto rowof = [&](int sl) -> int {
        return (sl < NSL) ? ((c0 - 1 + sl) & 255) : ((257 - c0 - (sl - NSL)) & 255);
    };

    const float2* in = g_buf1 + (size_t)sig * N2;

    // tables
    if (tid < 256) {
        float sv, cv;
        sincospif(-(float)tid / 256.0f, &sv, &cv);
        T[tid] = make_float2(cv, sv);
    } else if (tid < 256 + 36) {
        int sl = tid - 256;
        float sv, cv;
        sincospif(-(float)rowof(sl) / 65536.0f, &sv, &cv);
        WR[sl] = make_float2(cv, sv);
    }
    // load 36 rows (128-bit global loads)
    for (int idx = tid; idx < 36*128; idx += 512) {
        int sl = idx >> 7, cc = idx & 127;
        float4 t = *reinterpret_cast<const float4*>(in + rowof(sl)*256 + 2*cc);
        ZS[sl*RSZ + 2*cc]     = make_float2(t.x, t.y);
        ZS[sl*RSZ + 2*cc + 1] = make_float2(t.z, t.w);
    }
    __syncthreads();

    // phase 1: forward FFT over cols for 36 rows (32 + 4)
    {
        int w = tid >> 5, lane = tid & 31, n1 = lane & 15;
        int hw = 2*w + (lane >> 4);                  // 0..31
        fft256p<-1>(ZS + hw*RSZ, n1);
        if (hw < 4) fft256p<-1>(ZS + (32 + hw)*RSZ, n1);
    }
    __syncthreads();

    // phase 2: pair-owned gained X + magnitudes, in place.
#pragma unroll
    for (int t = tid; t < NSL*256; t += 512) {
        int sl = t >> 8, c = t & 255;
        int r  = rowof(sl);
        int ps = sl + NSL;
        int cm = (r == 0) ? ((256 - c) & 255) : (255 - c);
        if (r == 0 && c == 0) {
            float2 z0 = ZS[0];
            float X0 = (z0.x + z0.y) * g_gainT[0];
            float XN = (z0.x - z0.y) * g_g65536;
            ZS[sl*RSZ]    = make_float2(X0, 0.f);
            ZS[ps*RSZ]    = make_float2(XN, 0.f);
            MS[sl*MSS]    = fabsf(X0);
            MS[ps*MSS]    = fabsf(XN);
            SC[2] = fabsf(XN);
            continue;
        }
        float2 zj = ZS[sl*RSZ + c];
        float2 zm = ZS[ps*RSZ + cm];
        float Er = 0.5f*(zj.x + zm.x), Ei = 0.5f*(zj.y - zm.y);
        float Or = 0.5f*(zj.y + zm.y), Oi = -0.5f*(zj.x - zm.x);
        float2 W = cmulf(WR[sl], T[c]);
        float wor = W.x*Or - W.y*Oi, woi = W.x*Oi + W.y*Or;
        int rm = (256 - r) & 255;
        float gp = g_gainT[(r  << 8) + c];
        float gm = g_gainT[(rm << 8) + cm];
        float XPr = gp*(Er + wor), XPi = gp*(Ei + woi);
        float XMr = gm*(Er - wor), XMi = -gm*(Ei - woi);   // conj applied
        ZS[sl*RSZ + c]  = make_float2(XPr, XPi);
        ZS[ps*RSZ + cm] = make_float2(XMr, XMi);
        MS[sl*MSS + c]  = sqrtf(XPr*XPr + XPi*XPi);
        MS[ps*MSS + cm] = sqrtf(XMr*XMr + XMi*XMi);
    }
    __syncthreads();

    // phase 3: smooth-rescale + c2r combine, write both Zi in place.
#pragma unroll
    for (int t = tid; t < NC*256; t += 512) {
        int st = (t >> 8) + 1;        // 1..16 (central rows)
        int c  = t & 255;
        int ps = st + NSL;
        int cm = 255 - c;
        float2 a0 = ZS[st*RSZ + c];
        float2 b0 = ZS[ps*RSZ + cm];
        float magP = MS[st*MSS + c];
        float magM = MS[ps*MSS + cm];
        float msP = 0.7f*magP + 0.15f*MS[(st-1)*MSS + c] + 0.15f*MS[(st+1)*MSS + c];
        float nbM;                     // mag at jm+1
        if (Bx == 0 && st == 1)
            nbM = (c == 0) ? SC[2] : MS[(256 - c)];           // row 0, col 256-c
        else
            nbM = MS[(ps-1)*MSS + cm];
        float msM = 0.7f*magM + 0.15f*nbM + 0.15f*MS[(ps+1)*MSS + cm];
        float2 a, b;
        if (magP > 0.f) { float rr = msP / magP; a = make_float2(a0.x*rr, a0.y*rr); }
        else a = make_float2(msP, 0.f);
        if (magM > 0.f) { float rr = msM / magM; b = make_float2(b0.x*rr, b0.y*rr); }
        else b = make_float2(msM, 0.f);
        float2 W = cmulf(WR[st], T[c]);
        float er = 0.5f*(a.x + b.x);
        float ei = 0.5f*(a.y - b.y);
        float dr = 0.5f*(a.x - b.x);
        float di = 0.5f*(a.y + b.y);
        float orr = W.x*dr + W.y*di;
        float oi  = W.x*di - W.y*dr;
        ZS[st*RSZ + c]  = make_float2((er - oi)*inv, (ei + orr)*inv);
        ZS[ps*RSZ + cm] = make_float2((er + oi)*inv, (orr - ei)*inv);
    }
    if (Bx == 0 && tid < 256) {
        int c = tid;
        if (c == 0) {
            float X0 = ZS[0].x;
            float XN = ZS[NSL*RSZ].x;
            ZS[0] = make_float2(0.5f*(X0 + XN)*inv, 0.5f*(X0 - XN)*inv);
        } else {
            float2 a0 = ZS[c];                            // row 0, bin 256c
            float2 b0 = ZS[NSL*RSZ + (256 - c)];          // bin 65536-256c
            float magP = MS[c];
            float magM = MS[NSL*MSS + (256 - c)];
            float msP = 0.7f*magP + 0.15f*MS[(NSL+1)*MSS + (c-1)] + 0.15f*MS[MSS + c];
            float msM = 0.7f*magM + 0.15f*MS[(NSL+1)*MSS + (255 - c)] + 0.15f*MS[MSS + (256 - c)];
            float2 a, b;
            if (magP > 0.f) { float rr = msP / magP; a = make_float2(a0.x*rr, a0.y*rr); }
            else a = make_float2(msP, 0.f);
            if (magM > 0.f) { float rr = msM / magM; b = make_float2(b0.x*rr, b0.y*rr); }
            else b = make_float2(msM, 0.f);
            float2 W = T[c];
            float er = 0.5f*(a.x + b.x);
            float ei = 0.5f*(a.y - b.y);
            float dr = 0.5f*(a.x - b.x);
            float di = 0.5f*(a.y + b.y);
            float orr = W.x*dr + W.y*di;
            float oi  = W.x*di - W.y*dr;
            ZS[c] = make_float2((er - oi)*inv, (ei + orr)*inv);
        }
    }
    __syncthreads();

    // phase 4: inverse FFT over c (slots 1..16, 19..34 -> 32 half-warps full)
    {
        int w = tid >> 5, lane = tid & 31, n1 = lane & 15;
        int hw = 2*w + (lane >> 4);                  // 0..31
        int sl = (hw < 16) ? (hw + 1) : (hw + 3);    // 1..16, 19..34
        fft256p<1>(ZS + sl*RSZ, n1);
        if (Bx == 0 && w == 0) fft256p<1>(ZS, n1);   // slot 0 (dup halves, benign)
    }
    __syncthreads();

    // phase 5: twiddle * e^{+2pi i d a/65536}, write buf2[a*256+d] (coalesced in d)
    float2* out = g_buf2 + (size_t)sig * N2;
    {
        int g  = tid >> 8;             // 0: fw rows, 1: mirror rows
        int u  = tid & 255;
        int rl = u & 15;               // d offset (consecutive across lanes)
        int a0 = u >> 4;               // 0..15
        int sl, d;
        if (g == 0) { sl = 1 + rl;        d = c0 + rl; }
        else        { sl = NSL + 1 + rl;  d = (256 - c0 - rl) & 255; }
        float sv, cv;
        sincospif((float)(d * a0) / 32768.0f, &sv, &cv);
        float2 wv = make_float2(cv, sv);
        sincospif((float)d / 2048.0f, &sv, &cv);
        float2 wstep = make_float2(cv, sv);           // e^{+2pi i 16 d/65536}
#pragma unroll
        for (int it = 0; it < 16; it++) {
            int a = a0 + 16*it;
            float2 v = ZS[sl*RSZ + a];
            out[a * 256 + d] = cmulf(v, wv);
            wv = cmulf(wv, wstep);
        }
    }
    if (Bx == 0 && tid < 256) {
        out[tid * 256 + 0] = ZS[tid];   // row 0, twiddle = 1
    }
}

// ---------------------------------------------------------------------------
// Inverse pass 2: 16 rows a per CTA: IFFT over d -> z[a+256b]; write y.
// ---------------------------------------------------------------------------
__global__ __launch_bounds__(256) void ki2(float* __restrict__ y) {
    __shared__ float2 sA[16 * RS];
    int tid = threadIdx.x;
    int s   = blockIdx.y;
    int A0  = blockIdx.x * 16;
    const float2* in = g_buf2 + (size_t)s * N2;
    for (int idx = tid; idx < 2048; idx += 256) {
        int row = idx >> 7, cc = idx & 127;
        float4 t = *reinterpret_cast<const float4*>(in + (A0 + row)*256 + 2*cc);
        sA[row*RS + 2*cc]     = make_float2(t.x, t.y);
        sA[row*RS + 2*cc + 1] = make_float2(t.z, t.w);
    }
    __syncthreads();
    {
        int w = tid >> 5, lane = tid & 31;
        fft256p<1>(sA + (2*w + (lane >> 4)) * RS, lane & 15);
    }
    __syncthreads();
    float* ys = y + (size_t)s * LSIG;
    for (int idx = tid; idx < 4096; idx += 256) {
        int al = idx & 15, b = idx >> 4;
        int n  = A0 + al + (b << 8);
        int i2 = 2 * n;
        float2 v = sA[al * RS + b];
        if (i2 <= 65536) ys[i2] = v.x;
        if (i2 <  65536) ys[i2 + 1] = v.y;
    }
}

// ---------------------------------------------------------------------------
extern "C" void kernel_launch(void* const* d_in, const int* in_sizes, int n_in,
                              void* d_out, int out_size) {
    const float* x  = (const float*)d_in[0];
    const float* bw = (const float*)d_in[1];
    const float* fw = (const float*)d_in[2];
    const float* hp = (const float*)d_in[3];
    const float* b1 = (const float*)d_in[5];
    const float* W2 = (const float*)d_in[6];
    const float* b2 = (const float*)d_in[7];
    const float* W3 = (const float*)d_in[8];
    const float* b3 = (const float*)d_in[9];
    float* y = (float*)d_out;

    const int KMID_SMEM = (36*RSZ + 256 + 36) * (int)sizeof(float2)
                        + (36*MSS + 4) * (int)sizeof(float);
    cudaFuncSetAttribute(kmid, cudaFuncAttributeMaxDynamicSharedMemorySize, KMID_SMEM);

    kpm0<<<1, 32>>>(b1, W2, b2, W3, b3);
    kpmr<<<64, 256>>>(hp);
    kpm2<<<1, 32>>>();
    kgain<<<257, 256>>>(bw, fw);
    kf1<<<dim3(16, NSIG), 256>>>(x);
    kmid<<<dim3(8, NSIG), 512, KMID_SMEM>>>();
    ki2<<<dim3(16, NSIG), 256>>>(y);
}

// round 16
// speedup vs baseline: 1.6214x; 1.0110x over previous
#include <cuda_runtime.h>
#include <math.h>

// Problem constants
#define NSIG 256          // B*C = 128*2 signals
#define LSIG 65537        // signal length (== RLEN)
#define N2   65536        // packed complex FFT length (NFFT/2)
#define RS   257          // smem row stride in float2 (kf1/ki2)
#define RSZ  257          // smem row stride in float2 (kmid)
#define MSS  257          // magnitude row stride (floats)
#define NC   16           // central rows per kmid block
#define NSL  18           // forward slots (NC + 2 halos)

// Scratch (allowed: __device__ globals, no allocation)
__device__ __align__(16) float2 g_buf1[(size_t)NSIG * N2];   // 134 MB
__device__ __align__(16) float2 g_buf2[(size_t)NSIG * N2];   // 134 MB
__device__ float  g_gainT[65536];              // gain transposed: [r*256+c] = gain[r+256c]
__device__ float  g_g65536;                    // gain at bin 65536
__device__ float  g_part[64];

__device__ __forceinline__ float2 cmulf(float2 a, float2 b) {
    return make_float2(a.x*b.x - a.y*b.y, a.x*b.y + a.y*b.x);
}

// ---------------------------------------------------------------------------
// Packed f32x2 complex helpers (sm_103a PTX-only 2-wide fp32 ops).
// ---------------------------------------------------------------------------
typedef unsigned long long u64c;
#define NEG1C 0xBF800000BF800000ULL   // packed (-1.0f, -1.0f)

__device__ __forceinline__ u64c pk2(float lo, float hi) {
    u64c r; asm("mov.b64 %0, {%1, %2};" : "=l"(r) : "f"(lo), "f"(hi)); return r;
}
__device__ __forceinline__ float2 u2f(u64c p) {
    float2 v; asm("mov.b64 {%0, %1}, %2;" : "=f"(v.x), "=f"(v.y) : "l"(p)); return v;
}
__device__ __forceinline__ u64c addp(u64c a, u64c b) {
    u64c r; asm("add.rn.f32x2 %0, %1, %2;" : "=l"(r) : "l"(a), "l"(b)); return r;
}
__device__ __forceinline__ u64c mulp(u64c a, u64c b) {
    u64c r; asm("mul.rn.f32x2 %0, %1, %2;" : "=l"(r) : "l"(a), "l"(b)); return r;
}
__device__ __forceinline__ u64c fmap(u64c a, u64c b, u64c c) {
    u64c r; asm("fma.rn.f32x2 %0, %1, %2, %3;" : "=l"(r) : "l"(a), "l"(b), "l"(c)); return r;
}
__device__ __forceinline__ u64c swapp(u64c a) {
    float lo, hi; asm("mov.b64 {%0, %1}, %2;" : "=f"(lo), "=f"(hi) : "l"(a));
    return pk2(hi, lo);
}

// ---------------------------------------------------------------------------
// Packed register-resident 16-point FFT (Stockham radix-2, natural order).
// ---------------------------------------------------------------------------
template<int SGN, int M>
__device__ __forceinline__ void fstage16p(const u64c* A, u64c* B) {
    const float CU[8] = {1.f, 0.92387953251f, 0.70710678119f, 0.38268343236f,
                         0.f, -0.38268343236f, -0.70710678119f, -0.92387953251f};
    const float SU[8] = {0.f, 0.38268343236f, 0.70710678119f, 0.92387953251f,
                         1.f, 0.92387953251f, 0.70710678119f, 0.38268343236f};
#pragma unroll
    for (int t = 0; t < 8; t++) {
        int u = t & ~(M - 1);
        int o = t + u;
        u64c c0 = A[t], c1 = A[t + 8];
        u64c s = addp(c0, c1);
        u64c d = fmap(c1, (u64c)NEG1C, c0);
        B[o] = s;
        if (u == 0) {
            B[o + M] = d;
        } else {
            float wr = CU[u], wi = (float)SGN * SU[u];
            u64c wrr = pk2(wr, wr);
            u64c wsp = pk2(-wi, wi);
            B[o + M] = fmap(swapp(d), wsp, mulp(d, wrr));
        }
    }
}

template<int SGN>
__device__ __forceinline__ void fft16rp(u64c* v) {
    u64c b[16];
    fstage16p<SGN, 1>(v, b);
    fstage16p<SGN, 2>(b, v);
    fstage16p<SGN, 4>(v, b);
    fstage16p<SGN, 8>(b, v);   // result back in v
}

// First-stage-pruned variant: v[9..15] known zero (v[8] may be nonzero).
template<int SGN>
__device__ __forceinline__ void fft16rp_half(u64c* v) {
    const float CU[8] = {1.f, 0.92387953251f, 0.70710678119f, 0.38268343236f,
                         0.f, -0.38268343236f, -0.70710678119f, -0.92387953251f};
    const float SU[8] = {0.f, 0.38268343236f, 0.70710678119f, 0.92387953251f,
                         1.f, 0.92387953251f, 0.70710678119f, 0.38268343236f};
    u64c b[16];
    // stage M=1: t=0 full butterfly; t=1..7 have c1 == 0
    b[0] = addp(v[0], v[8]);
    b[1] = fmap(v[8], (u64c)NEG1C, v[0]);
#pragma unroll
    for (int t = 1; t < 8; t++) {
        u64c c0 = v[t];
        b[2*t] = c0;
        float wr = CU[t], wi = (float)SGN * SU[t];
        b[2*t+1] = fmap(swapp(c0), pk2(-wi, wi), mulp(c0, pk2(wr, wr)));
    }
    fstage16p<SGN, 2>(b, v);
    fstage16p<SGN, 4>(v, b);
    fstage16p<SGN, 8>(b, v);   // result back in v
}

// ---------------------------------------------------------------------------
// 256-point FFT of one row (half-warp per row). 16x16 decomposition,
// 2 smem round trips, XOR-swizzled intermediate, recurrence twiddles,
// packed-f32x2 radix-16 cores. HALF: input cols >= 129 known zero.
// ---------------------------------------------------------------------------
template<int SGN, bool HALF>
__device__ __forceinline__ void fft256p(float2* row, int n1) {
    u64c v[16];
    if (HALF) {
#pragma unroll
        for (int j = 0; j < 9; j++) { float2 t = row[n1 + 16*j]; v[j] = pk2(t.x, t.y); }
#pragma unroll
        for (int j = 9; j < 16; j++) v[j] = 0ULL;
        fft16rp_half<SGN>(v);
    } else {
#pragma unroll
        for (int j = 0; j < 16; j++) { float2 t = row[n1 + 16*j]; v[j] = pk2(t.x, t.y); }
        fft16rp<SGN>(v);
    }
    float si, co;
    sincospif((float)SGN * (float)n1 * (1.0f/128.0f), &si, &co);
    float2 w1 = make_float2(co, si);
    float2 wv = w1;
#pragma unroll
    for (int k2 = 1; k2 < 16; k2++) {
        float2 t = u2f(v[k2]);
        v[k2] = pk2(t.x*wv.x - t.y*wv.y, t.x*wv.y + t.y*wv.x);
        wv = cmulf(wv, w1);
    }
    __syncwarp();
#pragma unroll
    for (int k2 = 0; k2 < 16; k2++) row[16*k2 + (n1 ^ k2)] = u2f(v[k2]);
    __syncwarp();
    int k2 = n1;
    u64c u[16];
#pragma unroll
    for (int j = 0; j < 16; j++) { float2 t = row[16*k2 + (j ^ k2)]; u[j] = pk2(t.x, t.y); }
    fft16rp<SGN>(u);
    __syncwarp();
#pragma unroll
    for (int k1 = 0; k1 < 16; k1++) row[k2 + 16*k1] = u2f(u[k1]);
    __syncwarp();
}

// ---------------------------------------------------------------------------
// kpmr: 64 blocks; each block redundantly computes the tiny MLP mod_depth,
// then accumulates its partial chord sum into g_part[blockIdx].
// ---------------------------------------------------------------------------
__global__ __launch_bounds__(256) void kpmr(const float* __restrict__ hp,
                                            const float* __restrict__ b1,
                                            const float* __restrict__ W2,
                                            const float* __restrict__ b2,
                                            const float* __restrict__ W3,
                                            const float* __restrict__ b3) {
    __shared__ float aj[16];
    __shared__ float red[256];
    int tid = threadIdx.x;
    if (tid < 16) {
        float a = b2[tid];
        for (int i = 0; i < 32; i++) a += fmaxf(b1[i], 0.0f) * W2[i*16 + tid];
        aj[tid] = fmaxf(a, 0.0f);
    }
    __syncthreads();
    float md = b3[1];
#pragma unroll
    for (int j = 0; j < 16; j++) md += aj[j] * W3[j*8 + 1];
    float acc = 0.0f;
    for (int t = blockIdx.x * 256 + tid; t < LSIG; t += 64*256) {
        float tf = (float)t;
        int idx = ((int)(tf * 8.0f / 65537.0f)) & 7;
        float sv = sinf(6.2831853f * tf / 65537.0f);
        float cs = hp[idx*4] + hp[idx*4+1] + hp[idx*4+2] + hp[idx*4+3];
        acc += cs * (1.0f + md * sv);
    }
    red[tid] = acc;
    __syncthreads();
    for (int st = 128; st > 0; st >>= 1) {
        if (tid < st) red[tid] += red[tid + st];
        __syncthreads();
    }
    if (tid == 0) g_part[blockIdx.x] = red[0];
}

// ---------------------------------------------------------------------------
// gain kernel: inlines the g_part reduce (fixed order, deterministic),
// powf -> constant table. Writes transposed gain + bin-65536 scalar.
// ---------------------------------------------------------------------------
__global__ __launch_bounds__(256) void kgain(const float* __restrict__ bw,
                                             const float* __restrict__ fw) {
    __shared__ float spm;
    int tid = threadIdx.x;
    if (tid == 0) {
        float s = 0.0f;
        for (int i = 0; i < 64; i++) s += g_part[i];   // fixed order
        spm = s / (65537.0f * 4.0f);
    }
    __syncthreads();
    int i = blockIdx.x * 256 + tid;
    if (i > 65536) return;
    float f  = (float)((double)i * (22050.0 / 131072.0));
    float ti = (float)i;
    float g = 1.0f;
    const float lo[6] = {1.0f, 4.0f, 8.0f, 13.0f, 30.0f, 100.0f};
    const float hi[6] = {4.0f, 8.0f, 13.0f, 30.0f, 100.0f, 200.0f};
#pragma unroll
    for (int b = 0; b < 6; b++) {
        if (f >= lo[b] && f <= hi[b]) {
            float c  = 0.5f * (lo[b] + hi[b]);
            float sg = (hi[b] - lo[b]) * 0.25f;
            float z  = (f - c) / sg;
            float m  = expf(-0.5f * z * z);
            float tm = sinf(6.2831853f * c * ti / 22050.0f);
            g *= 1.0f + m * bw[b] * (1.0f + 0.2f * tm);
        }
    }
    float pm = spm;
    const float sf[8] = {7.83f, 528.0f, 396.0f, 2.5f, 14.1f, 432.0f, 6.0f, 30.0f};
    const float im12[6] = {0.f, 1.0f, 0.43527528f, 0.26758051f, 0.18946457f, 0.14495593f};
#pragma unroll
    for (int j = 0; j < 8; j++) {
#pragma unroll
        for (int m = 1; m <= 5; m++) {
            double hf = (double)sf[j] * (double)m;
            int hidx = (int)floor(hf * (131072.0 / 22050.0) + 0.5);
            int d = i - hidx;
            if (d >= -15 && d <= 15) {
                float win = expf(-0.5f * (float)(d*d) / 25.0f);
                float enh = fw[j] * win * im12[m] * (1.0f + pm);
                g *= 1.0f + enh;
            }
        }
    }
    if (i == 65536) g_g65536 = g;
    else g_gainT[(i & 255) * 256 + (i >> 8)] = g;
}

// ---------------------------------------------------------------------------
// Forward pass 1: 16 rows a per CTA: FFT over b of z[a+256b], * W^{ad},
// write transposed to buf1[d*256+a]. Twiddle via recurrence (2 sincospif).
// Uses zero-pruned FFT (input cols >= 129 all zero).
// ---------------------------------------------------------------------------
__global__ __launch_bounds__(256) void kf1(const float* __restrict__ x) {
    __shared__ float2 sA[16 * RS];
    int tid = threadIdx.x;
    int s   = blockIdx.y;
    int A0  = blockIdx.x * 16;
    const float* xs = x + (size_t)s * LSIG;
    for (int idx = tid; idx < 4096; idx += 256) {
        int al = idx & 15, b = idx >> 4;
        int n  = A0 + al + (b << 8);
        int i2 = 2 * n;
        float re = (i2 <= 65536) ? xs[i2] : 0.0f;
        float im = (i2 <  65536) ? xs[i2 + 1] : 0.0f;
        sA[al * RS + b] = make_float2(re, im);
    }
    __syncthreads();
    {
        int w = tid >> 5, lane = tid & 31;
        fft256p<-1, true>(sA + (2*w + (lane >> 4)) * RS, lane & 15);
    }
    __syncthreads();
    float2* out = g_buf1 + (size_t)s * N2;
    {
        int al = tid & 15;
        int d0 = tid >> 4;            // 0..15
        int a  = A0 + al;
        float sv, cv;
        sincospif(-(float)(a * d0) / 32768.0f, &sv, &cv);
        float2 wv = make_float2(cv, sv);              // e^{-2pi i a d0/65536}
        sincospif(-(float)a / 2048.0f, &sv, &cv);
        float2 wstep = make_float2(cv, sv);           // e^{-2pi i a*16/65536}
#pragma unroll
        for (int it = 0; it < 16; it++) {
            int d = d0 + 16 * it;
            float2 v = sA[al * RS + d];
            out[d * 256 + a] = cmulf(v, wv);
            wv = cmulf(wv, wstep);
        }
    }
}

// ---------------------------------------------------------------------------
// FUSED middle kernel: FFT over a + spectral + IFFT over c.
// Grid (8, NSIG), 512 threads. Block Bx: central rows c0..c0+15 (c0=16Bx+1),
// halos c0-1, c0+16, and all mirror rows: 36 slots (fw 0..17, mir 18..35).
// Pair ownership; recurrence twiddles; coalesced phase-5 stores.
// ---------------------------------------------------------------------------
__global__ __launch_bounds__(512, 2) void kmid() {
    extern __shared__ float2 smp[];
    float2* ZS = smp;                 // 36*RSZ  (Z -> gained X -> Zi)
    float2* T  = ZS + 36*RSZ;         // 256: e^{-i pi c/256}
    float2* WR = T + 256;             // 36:  e^{-i pi rowof(sl)/65536}
    float*  MS = (float*)(WR + 36);   // 36*MSS magnitudes
    float*  SC = MS + 36*MSS;         // [2] = |X[65536]|

    const int tid = threadIdx.x;
    const int sig = blockIdx.y;
    const int Bx  = blockIdx.x;
    const int c0  = NC*Bx + 1;
    const float inv = 1.0f / 65536.0f;

    auto rowof = [&](int sl) -> int {
        return (sl < NSL) ? ((c0 - 1 + sl) & 255) : ((257 - c0 - (sl - NSL)) & 255);
    };

    const float2* in = g_buf1 + (size_t)sig * N2;

    // tables
    if (tid < 256) {
        float sv, cv;
        sincospif(-(float)tid / 256.0f, &sv, &cv);
        T[tid] = make_float2(cv, sv);
    } else if (tid < 256 + 36) {
        int sl = tid - 256;
        float sv, cv;
        sincospif(-(float)rowof(sl) / 65536.0f, &sv, &cv);
        WR[sl] = make_float2(cv, sv);
    }
    // load 36 rows (128-bit global loads)
    for (int idx = tid; idx < 36*128; idx += 512) {
        int sl = idx >> 7, cc = idx & 127;
        float4 t = *reinterpret_cast<const float4*>(in + rowof(sl)*256 + 2*cc);
        ZS[sl*RSZ + 2*cc]     = make_float2(t.x, t.y);
        ZS[sl*RSZ + 2*cc + 1] = make_float2(t.z, t.w);
    }
    __syncthreads();

    // phase 1: forward FFT over cols for 36 rows (32 + 4)
    {
        int w = tid >> 5, lane = tid & 31, n1 = lane & 15;
        int hw = 2*w + (lane >> 4);                  // 0..31
        fft256p<-1, false>(ZS + hw*RSZ, n1);
        if (hw < 4) fft256p<-1, false>(ZS + (32 + hw)*RSZ, n1);
    }
    __syncthreads();

    // phase 2: pair-owned gained X + magnitudes, in place.
#pragma unroll
    for (int t = tid; t < NSL*256; t += 512) {
        int sl = t >> 8, c = t & 255;
        int r  = rowof(sl);
        int ps = sl + NSL;
        int cm = (r == 0) ? ((256 - c) & 255) : (255 - c);
        if (r == 0 && c == 0) {
            float2 z0 = ZS[0];
            float X0 = (z0.x + z0.y) * g_gainT[0];
            float XN = (z0.x - z0.y) * g_g65536;
            ZS[sl*RSZ]    = make_float2(X0, 0.f);
            ZS[ps*RSZ]    = make_float2(XN, 0.f);
            MS[sl*MSS]    = fabsf(X0);
            MS[ps*MSS]    = fabsf(XN);
            SC[2] = fabsf(XN);
            continue;
        }
        float2 zj = ZS[sl*RSZ + c];
        float2 zm = ZS[ps*RSZ + cm];
        float Er = 0.5f*(zj.x + zm.x), Ei = 0.5f*(zj.y - zm.y);
        float Or = 0.5f*(zj.y + zm.y), Oi = -0.5f*(zj.x - zm.x);
        float2 W = cmulf(WR[sl], T[c]);
        float wor = W.x*Or - W.y*Oi, woi = W.x*Oi + W.y*Or;
        int rm = (256 - r) & 255;
        float gp = g_gainT[(r  << 8) + c];
        float gm = g_gainT[(rm << 8) + cm];
        float XPr = gp*(Er + wor), XPi = gp*(Ei + woi);
        float XMr = gm*(Er - wor), XMi = -gm*(Ei - woi);   // conj applied
        ZS[sl*RSZ + c]  = make_float2(XPr, XPi);
        ZS[ps*RSZ + cm] = make_float2(XMr, XMi);
        MS[sl*MSS + c]  = sqrtf(XPr*XPr + XPi*XPi);
        MS[ps*MSS + cm] = sqrtf(XMr*XMr + XMi*XMi);
    }
    __syncthreads();

    // phase 3: smooth-rescale + c2r combine, write both Zi in place.
#pragma unroll
    for (int t = tid; t < NC*256; t += 512) {
        int st = (t >> 8) + 1;        // 1..16 (central rows)
        int c  = t & 255;
        int ps = st + NSL;
        int cm = 255 - c;
        float2 a0 = ZS[st*RSZ + c];
        float2 b0 = ZS[ps*RSZ + cm];
        float magP = MS[st*MSS + c];
        float magM = MS[ps*MSS + cm];
        float msP = 0.7f*magP + 0.15f*MS[(st-1)*MSS + c] + 0.15f*MS[(st+1)*MSS + c];
        float nbM;                     // mag at jm+1
        if (Bx == 0 && st == 1)
            nbM = (c == 0) ? SC[2] : MS[(256 - c)];           // row 0, col 256-c
        else
            nbM = MS[(ps-1)*MSS + cm];
        float msM = 0.7f*magM + 0.15f*nbM + 0.15f*MS[(ps+1)*MSS + cm];
        float2 a, b;
        if (magP > 0.f) { float rr = msP / magP; a = make_float2(a0.x*rr, a0.y*rr); }
        else a = make_float2(msP, 0.f);
        if (magM > 0.f) { float rr = msM / magM; b = make_float2(b0.x*rr, b0.y*rr); }
        else b = make_float2(msM, 0.f);
        float2 W = cmulf(WR[st], T[c]);
        float er = 0.5f*(a.x + b.x);
        float ei = 0.5f*(a.y - b.y);
        float dr = 0.5f*(a.x - b.x);
        float di = 0.5f*(a.y + b.y);
        float orr = W.x*dr + W.y*di;
        float oi  = W.x*di - W.y*dr;
        ZS[st*RSZ + c]  = make_float2((er - oi)*inv, (ei + orr)*inv);
        ZS[ps*RSZ + cm] = make_float2((er + oi)*inv, (orr - ei)*inv);
    }
    if (Bx == 0 && tid < 256) {
        int c = tid;
        if (c == 0) {
            float X0 = ZS[0].x;
            float XN = ZS[NSL*RSZ].x;
            ZS[0] = make_float2(0.5f*(X0 + XN)*inv, 0.5f*(X0 - XN)*inv);
        } else {
            float2 a0 = ZS[c];                            // row 0, bin 256c
            float2 b0 = ZS[NSL*RSZ + (256 - c)];          // bin 65536-256c
            float magP = MS[c];
            float magM = MS[NSL*MSS + (256 - c)];
            float msP = 0.7f*magP + 0.15f*MS[(NSL+1)*MSS + (c-1)] + 0.15f*MS[MSS + c];
            float msM = 0.7f*magM + 0.15f*MS[(NSL+1)*MSS + (255 - c)] + 0.15f*MS[MSS + (256 - c)];
            float2 a, b;
            if (magP > 0.f) { float rr = msP / magP; a = make_float2(a0.x*rr, a0.y*rr); }
            else a = make_float2(msP, 0.f);
            if (magM > 0.f) { float rr = msM / magM; b = make_float2(b0.x*rr, b0.y*rr); }
            else b = make_float2(msM, 0.f);
            float2 W = T[c];
            float er = 0.5f*(a.x + b.x);
            float ei = 0.5f*(a.y - b.y);
            float dr = 0.5f*(a.x - b.x);
            float di = 0.5f*(a.y + b.y);
            float orr = W.x*dr + W.y*di;
            float oi  = W.x*di - W.y*dr;
            ZS[c] = make_float2((er - oi)*inv, (ei + orr)*inv);
        }
    }
    __syncthreads();

    // phase 4: inverse FFT over c (slots 1..16, 19..34 -> 32 half-warps full)
    {
        int w = tid >> 5, lane = tid & 31, n1 = lane & 15;
        int hw = 2*w + (lane >> 4);                  // 0..31
        int sl = (hw < 16) ? (hw + 1) : (hw + 3);    // 1..16, 19..34
        fft256p<1, false>(ZS + sl*RSZ, n1);
        if (Bx == 0 && w == 0) fft256p<1, false>(ZS, n1);   // slot 0 (dup halves, benign)
    }
    __syncthreads();

    // phase 5: twiddle * e^{+2pi i d a/65536}, write buf2[a*256+d] (coalesced in d)
    float2* out = g_buf2 + (size_t)sig * N2;
    {
        int g  = tid >> 8;             // 0: fw rows, 1: mirror rows
        int u  = tid & 255;
        int rl = u & 15;               // d offset (consecutive across lanes)
        int a0 = u >> 4;               // 0..15
        int sl, d;
        if (g == 0) { sl = 1 + rl;        d = c0 + rl; }
        else        { sl = NSL + 1 + rl;  d = (256 - c0 - rl) & 255; }
        float sv, cv;
        sincospif((float)(d * a0) / 32768.0f, &sv, &cv);
        float2 wv = make_float2(cv, sv);
        sincospif((float)d / 2048.0f, &sv, &cv);
        float2 wstep = make_float2(cv, sv);           // e^{+2pi i 16 d/65536}
#pragma unroll
        for (int it = 0; it < 16; it++) {
            int a = a0 + 16*it;
            float2 v = ZS[sl*RSZ + a];
            out[a * 256 + d] = cmulf(v, wv);
            wv = cmulf(wv, wstep);
        }
    }
    if (Bx == 0 && tid < 256) {
        out[tid * 256 + 0] = ZS[tid];   // row 0, twiddle = 1
    }
}

// ---------------------------------------------------------------------------
// Inverse pass 2: 16 rows a per CTA: IFFT over d -> z[a+256b]; write y.
// ---------------------------------------------------------------------------
__global__ __launch_bounds__(256) void ki2(float* __restrict__ y) {
    __shared__ float2 sA[16 * RS];
    int tid = threadIdx.x;
    int s   = blockIdx.y;
    int A0  = blockIdx.x * 16;
    const float2* in = g_buf2 + (size_t)s * N2;
    for (int idx = tid; idx < 2048; idx += 256) {
        int row = idx >> 7, cc = idx & 127;
        float4 t = *reinterpret_cast<const float4*>(in + (A0 + row)*256 + 2*cc);
        sA[row*RS + 2*cc]     = make_float2(t.x, t.y);
        sA[row*RS + 2*cc + 1] = make_float2(t.z, t.w);
    }
    __syncthreads();
    {
        int w = tid >> 5, lane = tid & 31;
        fft256p<1, false>(sA + (2*w + (lane >> 4)) * RS, lane & 15);
    }
    __syncthreads();
    float* ys = y + (size_t)s * LSIG;
    for (int idx = tid; idx < 4096; idx += 256) {
        int al = idx & 15, b = idx >> 4;
        int n  = A0 + al + (b << 8);
        int i2 = 2 * n;
        float2 v = sA[al * RS + b];
        if (i2 <= 65536) ys[i2] = v.x;
        if (i2 <  65536) ys[i2 + 1] = v.y;
    }
}

// ---------------------------------------------------------------------------
extern "C" void kernel_launch(void* const* d_in, const int* in_sizes, int n_in,
                              void* d_out, int out_size) {
    const float* x  = (const float*)d_in[0];
    const float* bw = (const float*)d_in[1];
    const float* fw = (const float*)d_in[2];
    const float* hp = (const float*)d_in[3];
    const float* b1 = (const float*)d_in[5];
    const float* W2 = (const float*)d_in[6];
    const float* b2 = (const float*)d_in[7];
    const float* W3 = (const float*)d_in[8];
    const float* b3 = (const float*)d_in[9];
    float* y = (float*)d_out;

    const int KMID_SMEM = (36*RSZ + 256 + 36) * (int)sizeof(float2)
                        + (36*MSS + 4) * (int)sizeof(float);
    cudaFuncSetAttribute(kmid, cudaFuncAttributeMaxDynamicSharedMemorySize, KMID_SMEM);

    kpmr<<<64, 256>>>(hp, b1, W2, b2, W3, b3);
    kgain<<<257, 256>>>(bw, fw);
    kf1<<<dim3(16, NSIG), 256>>>(x);
    kmid<<<dim3(8, NSIG), 512, KMID_SMEM>>>();
    ki2<<<dim3(16, NSIG), 256>>>(y);
}